// round 1
// baseline (speedup 1.0000x reference)
#include <cuda_runtime.h>
#include <math.h>

#define NN   1024
#define ND   128
#define ED   16
#define MD   64
#define IND  272   // 2*ND + ED

// ---------------- scratch (no allocations allowed) ----------------
__device__ float g_HB[NN * MD];        // hi + b1
__device__ float g_HJ[NN * MD];        // hj
__device__ float g_S [NN * MD];        // sum_j A_ij * relu(pre_ij)
__device__ float g_deg[NN];            // degree (float)
__device__ float g_M [NN * MD];        // S @ W2^T + deg*b2
__device__ float g_GI[NN * 3 * ND];
__device__ float g_GH[NN * 3 * ND];
__device__ float g_H1[NN * ND];
__device__ float g_H2[NN * ND];

// ---------------- generic small GEMM: C = A @ W^T (+ bias*rowscale) ----------------
// A: n x k (lda), W: p x k (ldw), C: n x p (ldc). Grid: (p/64, n/64), 256 threads.
__global__ void gemm_bias_kernel(const float* __restrict__ A, int lda,
                                 const float* __restrict__ W, int ldw,
                                 const float* __restrict__ bias,
                                 const float* __restrict__ rowscale,
                                 float* __restrict__ C, int ldc,
                                 int k)
{
    __shared__ float As[64][33];
    __shared__ float Ws[64][33];
    const int tid  = threadIdx.x;
    const int row0 = blockIdx.y * 64;
    const int col0 = blockIdx.x * 64;
    const int tr = (tid >> 4) * 4;   // 16 row-groups of 4
    const int tc = (tid & 15) * 4;   // 16 col-groups of 4

    float acc[4][4] = {};

    for (int k0 = 0; k0 < k; k0 += 32) {
        #pragma unroll
        for (int l = 0; l < 2; l++) {
            int idx = tid + l * 256;       // 512 float4 slots
            int r   = idx >> 3;            // 0..63
            int c   = (idx & 7) * 4;       // 0..28
            float4 av = *(const float4*)&A[(size_t)(row0 + r) * lda + k0 + c];
            As[r][c+0] = av.x; As[r][c+1] = av.y; As[r][c+2] = av.z; As[r][c+3] = av.w;
            float4 wv = *(const float4*)&W[(size_t)(col0 + r) * ldw + k0 + c];
            Ws[r][c+0] = wv.x; Ws[r][c+1] = wv.y; Ws[r][c+2] = wv.z; Ws[r][c+3] = wv.w;
        }
        __syncthreads();
        #pragma unroll
        for (int kk = 0; kk < 32; kk++) {
            float a0 = As[tr+0][kk], a1 = As[tr+1][kk], a2 = As[tr+2][kk], a3 = As[tr+3][kk];
            float b0 = Ws[tc+0][kk], b1 = Ws[tc+1][kk], b2 = Ws[tc+2][kk], b3 = Ws[tc+3][kk];
            acc[0][0] = fmaf(a0,b0,acc[0][0]); acc[0][1] = fmaf(a0,b1,acc[0][1]);
            acc[0][2] = fmaf(a0,b2,acc[0][2]); acc[0][3] = fmaf(a0,b3,acc[0][3]);
            acc[1][0] = fmaf(a1,b0,acc[1][0]); acc[1][1] = fmaf(a1,b1,acc[1][1]);
            acc[1][2] = fmaf(a1,b2,acc[1][2]); acc[1][3] = fmaf(a1,b3,acc[1][3]);
            acc[2][0] = fmaf(a2,b0,acc[2][0]); acc[2][1] = fmaf(a2,b1,acc[2][1]);
            acc[2][2] = fmaf(a2,b2,acc[2][2]); acc[2][3] = fmaf(a2,b3,acc[2][3]);
            acc[3][0] = fmaf(a3,b0,acc[3][0]); acc[3][1] = fmaf(a3,b1,acc[3][1]);
            acc[3][2] = fmaf(a3,b2,acc[3][2]); acc[3][3] = fmaf(a3,b3,acc[3][3]);
        }
        __syncthreads();
    }

    #pragma unroll
    for (int r = 0; r < 4; r++) {
        int row = row0 + tr + r;
        float rs = rowscale ? rowscale[row] : 1.0f;
        #pragma unroll
        for (int c = 0; c < 4; c++) {
            int col = col0 + tc + c;
            float v = acc[r][c];
            if (bias) v = fmaf(bias[col], rs, v);
            C[(size_t)row * ldc + col] = v;
        }
    }
}

// ---------------- edge kernel: S[i,:] = sum_{j: A_ij=1} relu(hb_i + hj_j + E_ij@We^T) ----------------
// One block per node i, 256 threads = 8 warps. Warp w handles j = w, w+8, ...
// Lane owns m = lane and m = lane+32; We rows held in registers.
__global__ void edge_kernel(const float* __restrict__ HB, const float* __restrict__ HJ,
                            const float* __restrict__ E, const int* __restrict__ A,
                            const float* __restrict__ W1,
                            float* __restrict__ S, float* __restrict__ deg)
{
    const int i    = blockIdx.x;
    const int tid  = threadIdx.x;
    const int w    = tid >> 5;
    const int lane = tid & 31;

    __shared__ float hb_sh[MD];
    __shared__ float s_sh[8][MD];
    __shared__ float d_sh[8];

    if (tid < MD) hb_sh[tid] = HB[i * MD + tid];
    __syncthreads();

    // We rows for m = lane, lane+32 (W1 row m, cols [256..272))
    float we0[ED], we1[ED];
    {
        const float4* p0 = (const float4*)(W1 + (size_t)lane        * IND + 2 * ND);
        const float4* p1 = (const float4*)(W1 + (size_t)(lane + 32) * IND + 2 * ND);
        #pragma unroll
        for (int q = 0; q < 4; q++) {
            float4 v = p0[q];
            we0[4*q+0] = v.x; we0[4*q+1] = v.y; we0[4*q+2] = v.z; we0[4*q+3] = v.w;
            float4 u = p1[q];
            we1[4*q+0] = u.x; we1[4*q+1] = u.y; we1[4*q+2] = u.z; we1[4*q+3] = u.w;
        }
    }
    const float hb0 = hb_sh[lane];
    const float hb1 = hb_sh[lane + 32];

    float acc0 = 0.f, acc1 = 0.f, dcnt = 0.f;
    const int* Arow = A + (size_t)i * NN;

    for (int j = w; j < NN; j += 8) {
        if (Arow[j] == 0) continue;      // warp-uniform (j same across lanes)
        dcnt += 1.f;
        const float4* ep = (const float4*)(E + ((size_t)i * NN + j) * ED);
        float e[ED];
        #pragma unroll
        for (int q = 0; q < 4; q++) {
            float4 v = ep[q];
            e[4*q+0] = v.x; e[4*q+1] = v.y; e[4*q+2] = v.z; e[4*q+3] = v.w;
        }
        float v0 = hb0 + HJ[(size_t)j * MD + lane];
        float v1 = hb1 + HJ[(size_t)j * MD + lane + 32];
        #pragma unroll
        for (int q = 0; q < ED; q++) {
            v0 = fmaf(e[q], we0[q], v0);
            v1 = fmaf(e[q], we1[q], v1);
        }
        acc0 += fmaxf(v0, 0.f);
        acc1 += fmaxf(v1, 0.f);
    }

    s_sh[w][lane]      = acc0;
    s_sh[w][lane + 32] = acc1;
    if (lane == 0) d_sh[w] = dcnt;
    __syncthreads();

    if (tid < MD) {
        float s = 0.f;
        #pragma unroll
        for (int ww = 0; ww < 8; ww++) s += s_sh[ww][tid];
        S[i * MD + tid] = s;
    }
    if (tid == MD) {
        float d = 0.f;
        #pragma unroll
        for (int ww = 0; ww < 8; ww++) d += d_sh[ww];
        deg[i] = d;
    }
}

// ---------------- elementwise GRU update ----------------
__global__ void gru_kernel(const float* __restrict__ GI, const float* __restrict__ GH,
                           const float* __restrict__ Hprev, float* __restrict__ Hout)
{
    int idx = blockIdx.x * blockDim.x + threadIdx.x;   // NN*ND
    int i = idx >> 7;
    int d = idx & (ND - 1);
    const float* gi = GI + (size_t)i * 3 * ND;
    const float* gh = GH + (size_t)i * 3 * ND;
    float r = 1.f / (1.f + expf(-(gi[d]          + gh[d])));
    float z = 1.f / (1.f + expf(-(gi[ND + d]     + gh[ND + d])));
    float n = tanhf(gi[2 * ND + d] + r * gh[2 * ND + d]);
    float h = Hprev[idx];
    Hout[idx] = (1.f - z) * n + z * h;
}

// ---------------- launch ----------------
extern "C" void kernel_launch(void* const* d_in, const int* in_sizes, int n_in,
                              void* d_out, int out_size)
{
    const float* X    = (const float*)d_in[0];
    const int*   A    = (const int*)  d_in[1];
    const float* E    = (const float*)d_in[2];
    const float* W1   = (const float*)d_in[3];
    const float* b1   = (const float*)d_in[4];
    const float* W2   = (const float*)d_in[5];
    const float* b2   = (const float*)d_in[6];
    const float* W_ih = (const float*)d_in[7];
    const float* b_ih = (const float*)d_in[8];
    const float* W_hh = (const float*)d_in[9];
    const float* b_hh = (const float*)d_in[10];

    float *HB, *HJ, *S, *DEG, *M, *GI, *GH, *H1, *H2;
    cudaGetSymbolAddress((void**)&HB,  g_HB);
    cudaGetSymbolAddress((void**)&HJ,  g_HJ);
    cudaGetSymbolAddress((void**)&S,   g_S);
    cudaGetSymbolAddress((void**)&DEG, g_deg);
    cudaGetSymbolAddress((void**)&M,   g_M);
    cudaGetSymbolAddress((void**)&GI,  g_GI);
    cudaGetSymbolAddress((void**)&GH,  g_GH);
    cudaGetSymbolAddress((void**)&H1,  g_H1);
    cudaGetSymbolAddress((void**)&H2,  g_H2);

    const float* Hprev = X;
    for (int t = 0; t < 3; t++) {
        float* Hout = (t == 2) ? (float*)d_out : (t == 0 ? H1 : H2);

        // hi + b1  and  hj
        gemm_bias_kernel<<<dim3(1, 16), 256>>>(Hprev, ND, W1,      IND, b1,      nullptr, HB, MD, ND);
        gemm_bias_kernel<<<dim3(1, 16), 256>>>(Hprev, ND, W1 + ND, IND, nullptr, nullptr, HJ, MD, ND);

        // masked relu-sum over edges
        edge_kernel<<<NN, 256>>>(HB, HJ, E, A, W1, S, DEG);

        // M = S @ W2^T + deg * b2
        gemm_bias_kernel<<<dim3(1, 16), 256>>>(S, MD, W2, MD, b2, DEG, M, MD, MD);

        // gi = M @ W_ih^T + b_ih ; gh = H @ W_hh^T + b_hh
        gemm_bias_kernel<<<dim3(6, 16), 256>>>(M,     MD, W_ih, MD, b_ih, nullptr, GI, 3 * ND, MD);
        gemm_bias_kernel<<<dim3(6, 16), 256>>>(Hprev, ND, W_hh, ND, b_hh, nullptr, GH, 3 * ND, ND);

        // GRU update
        gru_kernel<<<(NN * ND) / 256, 256>>>(GI, GH, Hprev, Hout);

        Hprev = Hout;
    }
}

// round 4
// speedup vs baseline: 1.6624x; 1.6624x over previous
#include <cuda_runtime.h>
#include <math.h>

#define NN   1024
#define ND   128
#define ED   16
#define MD   64
#define IND  272   // 2*ND + ED
#define CW   512   // fused pre-GEMM width: 64 (HB) + 64 (HJ) + 384 (GH)

// ---------------- scratch (no allocations allowed) ----------------
__device__ float g_C   [NN * CW];      // [HB | HJ | GH] per node
__device__ float g_S   [NN * MD];      // sum_j A_ij * relu(pre_ij)
__device__ float g_deg [NN];           // degree (float)
__device__ float g_GI  [NN * 3 * ND];
__device__ float g_H1  [NN * ND];
__device__ float g_H2  [NN * ND];
__device__ float g_Wcat[CW * ND];      // [Wi; Wj; W_hh] packed, 512 x 128
__device__ float g_bcat[CW];           // [b1; 0; b_hh]
__device__ float g_Wc  [3 * ND * MD];  // W_ih @ W2, 384 x 64
__device__ float g_bc  [3 * ND];       // W_ih @ b2

// ---------------- pack kernel: build Wcat/bcat ----------------
__global__ void pack_kernel(const float* __restrict__ W1, const float* __restrict__ b1,
                            const float* __restrict__ W_hh, const float* __restrict__ b_hh,
                            float* __restrict__ Wcat, float* __restrict__ bcat)
{
    int idx = blockIdx.x * blockDim.x + threadIdx.x;   // 512*128 threads
    int r = idx >> 7;          // 0..511
    int c = idx & 127;
    float v;
    if (r < MD)            v = W1[(size_t)r * IND + c];              // Wi
    else if (r < 2 * MD)   v = W1[(size_t)(r - MD) * IND + ND + c];  // Wj
    else                   v = W_hh[(size_t)(r - 2 * MD) * ND + c];  // W_hh
    Wcat[idx] = v;
    if (idx < CW) {
        float b;
        if (idx < MD)          b = b1[idx];
        else if (idx < 2 * MD) b = 0.f;
        else                   b = b_hh[idx - 2 * MD];
        bcat[idx] = b;
    }
}

// ---------------- precompute Wc = W_ih @ W2, bc = W_ih @ b2 ----------------
__global__ void wc_kernel(const float* __restrict__ W_ih, const float* __restrict__ W2,
                          const float* __restrict__ b2,
                          float* __restrict__ Wc, float* __restrict__ bc)
{
    int bid = blockIdx.x;
    if (bid < 96) {
        int idx = bid * 256 + threadIdx.x;    // 384*64
        int r = idx >> 6;
        int s = idx & 63;
        float acc = 0.f;
        #pragma unroll 8
        for (int m = 0; m < MD; m++)
            acc = fmaf(W_ih[(size_t)r * MD + m], W2[(size_t)m * MD + s], acc);
        Wc[idx] = acc;
    } else {
        // BUGFIX (R3): cover all 384 rows with 256 threads
        for (int r = threadIdx.x; r < 3 * ND; r += blockDim.x) {
            float acc = 0.f;
            #pragma unroll 8
            for (int m = 0; m < MD; m++)
                acc = fmaf(W_ih[(size_t)r * MD + m], b2[m], acc);
            bc[r] = acc;
        }
    }
}

// ---------------- GEMM: C = A @ W^T + bias + rowscale*biasd ----------------
// A: n x k (lda), W: p x k (ldw), C: n x p (ldc). Grid: (p/64, n/64), 256 threads.
__global__ void gemm_kernel(const float* __restrict__ A, int lda,
                            const float* __restrict__ W, int ldw,
                            const float* __restrict__ bias,
                            const float* __restrict__ biasd,
                            const float* __restrict__ rowscale,
                            float* __restrict__ C, int ldc,
                            int k)
{
    __shared__ float As[64][33];
    __shared__ float Ws[64][33];
    const int tid  = threadIdx.x;
    const int row0 = blockIdx.y * 64;
    const int col0 = blockIdx.x * 64;
    const int tr = (tid >> 4) * 4;
    const int tc = (tid & 15) * 4;

    float acc[4][4] = {};

    for (int k0 = 0; k0 < k; k0 += 32) {
        #pragma unroll
        for (int l = 0; l < 2; l++) {
            int idx = tid + l * 256;
            int r   = idx >> 3;
            int c   = (idx & 7) * 4;
            float4 av = *(const float4*)&A[(size_t)(row0 + r) * lda + k0 + c];
            As[r][c+0] = av.x; As[r][c+1] = av.y; As[r][c+2] = av.z; As[r][c+3] = av.w;
            float4 wv = *(const float4*)&W[(size_t)(col0 + r) * ldw + k0 + c];
            Ws[r][c+0] = wv.x; Ws[r][c+1] = wv.y; Ws[r][c+2] = wv.z; Ws[r][c+3] = wv.w;
        }
        __syncthreads();
        #pragma unroll
        for (int kk = 0; kk < 32; kk++) {
            float a0 = As[tr+0][kk], a1 = As[tr+1][kk], a2 = As[tr+2][kk], a3 = As[tr+3][kk];
            float b0 = Ws[tc+0][kk], b1 = Ws[tc+1][kk], b2 = Ws[tc+2][kk], b3 = Ws[tc+3][kk];
            acc[0][0] = fmaf(a0,b0,acc[0][0]); acc[0][1] = fmaf(a0,b1,acc[0][1]);
            acc[0][2] = fmaf(a0,b2,acc[0][2]); acc[0][3] = fmaf(a0,b3,acc[0][3]);
            acc[1][0] = fmaf(a1,b0,acc[1][0]); acc[1][1] = fmaf(a1,b1,acc[1][1]);
            acc[1][2] = fmaf(a1,b2,acc[1][2]); acc[1][3] = fmaf(a1,b3,acc[1][3]);
            acc[2][0] = fmaf(a2,b0,acc[2][0]); acc[2][1] = fmaf(a2,b1,acc[2][1]);
            acc[2][2] = fmaf(a2,b2,acc[2][2]); acc[2][3] = fmaf(a2,b3,acc[2][3]);
            acc[3][0] = fmaf(a3,b0,acc[3][0]); acc[3][1] = fmaf(a3,b1,acc[3][1]);
            acc[3][2] = fmaf(a3,b2,acc[3][2]); acc[3][3] = fmaf(a3,b3,acc[3][3]);
        }
        __syncthreads();
    }

    #pragma unroll
    for (int r = 0; r < 4; r++) {
        int row = row0 + tr + r;
        float rs = rowscale ? rowscale[row] : 0.0f;
        #pragma unroll
        for (int c = 0; c < 4; c++) {
            int col = col0 + tc + c;
            float v = acc[r][c];
            if (bias)  v += bias[col];
            if (biasd) v = fmaf(biasd[col], rs, v);
            C[(size_t)row * ldc + col] = v;
        }
    }
}

// ---------------- edge kernel ----------------
// S[i,:] = sum_{j: A_ij=1} relu(HB_i + HJ_j + E_ij @ We^T)
// One block per i, 8 warps; warp w handles the contiguous range j in [w*128, w*128+128).
__global__ void edge_kernel(const float* __restrict__ C,   // HB at +0, HJ at +64, ld=CW
                            const float* __restrict__ E, const int* __restrict__ A,
                            const float* __restrict__ W1,
                            float* __restrict__ S, float* __restrict__ deg)
{
    const int i    = blockIdx.x;
    const int tid  = threadIdx.x;
    const int w    = tid >> 5;
    const int lane = tid & 31;

    __shared__ float s_sh[8][MD];
    __shared__ float d_sh[8];

    // We rows for m = lane, lane+32 (W1 row m, cols [256..272))
    float we0[ED], we1[ED];
    {
        const float4* p0 = (const float4*)(W1 + (size_t)lane        * IND + 2 * ND);
        const float4* p1 = (const float4*)(W1 + (size_t)(lane + 32) * IND + 2 * ND);
        #pragma unroll
        for (int q = 0; q < 4; q++) {
            float4 v = p0[q];
            we0[4*q+0] = v.x; we0[4*q+1] = v.y; we0[4*q+2] = v.z; we0[4*q+3] = v.w;
            float4 u = p1[q];
            we1[4*q+0] = u.x; we1[4*q+1] = u.y; we1[4*q+2] = u.z; we1[4*q+3] = u.w;
        }
    }
    const float hb0 = C[(size_t)i * CW + lane];
    const float hb1 = C[(size_t)i * CW + lane + 32];

    float acc0 = 0.f, acc1 = 0.f;
    int dcnt = 0;

    const int   jbase = w * 128;
    const int*  Arow  = A + (size_t)i * NN + jbase;
    const float* Erow = E + ((size_t)i * NN + jbase) * ED;

    for (int jj = 0; jj < 128; jj += 4) {
        int4 a4 = *(const int4*)&Arow[jj];     // warp-uniform
        #pragma unroll
        for (int u = 0; u < 4; u++) {
            int a = (u == 0) ? a4.x : (u == 1) ? a4.y : (u == 2) ? a4.z : a4.w;
            if (a == 0) continue;
            int j = jj + u;
            dcnt++;
            const float4* ep = (const float4*)(Erow + (size_t)j * ED);
            float e[ED];
            #pragma unroll
            for (int q = 0; q < 4; q++) {
                float4 v = ep[q];
                e[4*q+0] = v.x; e[4*q+1] = v.y; e[4*q+2] = v.z; e[4*q+3] = v.w;
            }
            const float* hjp = C + (size_t)(jbase + j) * CW + MD;
            float v0 = hb0 + hjp[lane];
            float v1 = hb1 + hjp[lane + 32];
            #pragma unroll
            for (int q = 0; q < ED; q++) {
                v0 = fmaf(e[q], we0[q], v0);
                v1 = fmaf(e[q], we1[q], v1);
            }
            acc0 += fmaxf(v0, 0.f);
            acc1 += fmaxf(v1, 0.f);
        }
    }

    s_sh[w][lane]      = acc0;
    s_sh[w][lane + 32] = acc1;
    if (lane == 0) d_sh[w] = (float)dcnt;
    __syncthreads();

    if (tid < MD) {
        float s = 0.f;
        #pragma unroll
        for (int ww = 0; ww < 8; ww++) s += s_sh[ww][tid];
        S[i * MD + tid] = s;
    }
    if (tid == MD) {
        float d = 0.f;
        #pragma unroll
        for (int ww = 0; ww < 8; ww++) d += d_sh[ww];
        deg[i] = d;
    }
}

// ---------------- elementwise GRU update ----------------
__global__ void gru_kernel(const float* __restrict__ GI, const float* __restrict__ C,
                           const float* __restrict__ Hprev, float* __restrict__ Hout)
{
    int idx = blockIdx.x * blockDim.x + threadIdx.x;   // NN*ND
    int i = idx >> 7;
    int d = idx & (ND - 1);
    const float* gi = GI + (size_t)i * 3 * ND;
    const float* gh = C + (size_t)i * CW + 2 * MD;     // GH section
    float r = 1.f / (1.f + __expf(-(gi[d]          + gh[d])));
    float z = 1.f / (1.f + __expf(-(gi[ND + d]     + gh[ND + d])));
    float narg = gi[2 * ND + d] + r * gh[2 * ND + d];
    float n = 1.f - 2.f / (__expf(2.f * narg) + 1.f);   // tanh
    float h = Hprev[idx];
    Hout[idx] = (1.f - z) * n + z * h;
}

// ---------------- launch ----------------
extern "C" void kernel_launch(void* const* d_in, const int* in_sizes, int n_in,
                              void* d_out, int out_size)
{
    const float* X    = (const float*)d_in[0];
    const int*   A    = (const int*)  d_in[1];
    const float* E    = (const float*)d_in[2];
    const float* W1   = (const float*)d_in[3];
    const float* b1   = (const float*)d_in[4];
    const float* W2   = (const float*)d_in[5];
    const float* b2   = (const float*)d_in[6];
    const float* W_ih = (const float*)d_in[7];
    const float* b_ih = (const float*)d_in[8];
    const float* W_hh = (const float*)d_in[9];
    const float* b_hh = (const float*)d_in[10];

    float *C, *S, *DEG, *GI, *H1, *H2, *Wcat, *bcat, *Wc, *bc;
    cudaGetSymbolAddress((void**)&C,    g_C);
    cudaGetSymbolAddress((void**)&S,    g_S);
    cudaGetSymbolAddress((void**)&DEG,  g_deg);
    cudaGetSymbolAddress((void**)&GI,   g_GI);
    cudaGetSymbolAddress((void**)&H1,   g_H1);
    cudaGetSymbolAddress((void**)&H2,   g_H2);
    cudaGetSymbolAddress((void**)&Wcat, g_Wcat);
    cudaGetSymbolAddress((void**)&bcat, g_bcat);
    cudaGetSymbolAddress((void**)&Wc,   g_Wc);
    cudaGetSymbolAddress((void**)&bc,   g_bc);

    // one-time packing (per call; cheap)
    pack_kernel<<<(CW * ND) / 256, 256>>>(W1, b1, W_hh, b_hh, Wcat, bcat);
    wc_kernel<<<97, 256>>>(W_ih, W2, b2, Wc, bc);

    const float* Hprev = X;
    for (int t = 0; t < 3; t++) {
        float* Hout = (t == 2) ? (float*)d_out : (t == 0 ? H1 : H2);

        // C = Hprev @ Wcat^T + bcat   -> [HB | HJ | GH]
        gemm_kernel<<<dim3(CW / 64, 16), 256>>>(Hprev, ND, Wcat, ND, bcat,
                                                nullptr, nullptr, C, CW, ND);

        // masked relu-sum over edges
        edge_kernel<<<NN, 256>>>(C, E, A, W1, S, DEG);

        // GI = S @ Wc^T + b_ih + deg*bc
        gemm_kernel<<<dim3((3 * ND) / 64, 16), 256>>>(S, MD, Wc, MD, b_ih,
                                                      bc, DEG, GI, 3 * ND, MD);

        // GRU update
        gru_kernel<<<(NN * ND) / 256, 256>>>(GI, C, Hprev, Hout);

        Hprev = Hout;
    }
}

// round 5
// speedup vs baseline: 1.8943x; 1.1395x over previous
#include <cuda_runtime.h>
#include <math.h>

#define NN   1024
#define ND   128
#define ED   16
#define MD   64
#define IND  272   // 2*ND + ED
#define CW   512   // fused pre-GEMM width: 64 (HB) + 64 (HJ) + 384 (GH)

// ---------------- scratch (no allocations allowed) ----------------
__device__ float g_C   [NN * CW];      // [HB | HJ | GH] per node
__device__ float g_S   [NN * MD];      // sum_j A_ij * relu(pre_ij)
__device__ float g_deg [NN];           // degree (float)
__device__ float g_GI  [NN * 3 * ND];
__device__ float g_H1  [NN * ND];
__device__ float g_H2  [NN * ND];
__device__ float g_Wcat[CW * ND];      // [Wi; Wj; W_hh] packed, 512 x 128
__device__ float g_bcat[CW];           // [b1; 0; b_hh]
__device__ float g_Wc  [3 * ND * MD];  // W_ih @ W2, 384 x 64
__device__ float g_bc  [3 * ND];       // W_ih @ b2
// Ep[i][j] packed: lane u32 holds bf16(ep[m=lane]) in low half, bf16(ep[m=lane+32]) hi.
__device__ unsigned g_Ep[(size_t)NN * NN * 32];   // 128 MB

// ---------------- pack kernel: build Wcat/bcat ----------------
__global__ void pack_kernel(const float* __restrict__ W1, const float* __restrict__ b1,
                            const float* __restrict__ W_hh, const float* __restrict__ b_hh,
                            float* __restrict__ Wcat, float* __restrict__ bcat)
{
    int idx = blockIdx.x * blockDim.x + threadIdx.x;
    int r = idx >> 7;
    int c = idx & 127;
    float v;
    if (r < MD)            v = W1[(size_t)r * IND + c];
    else if (r < 2 * MD)   v = W1[(size_t)(r - MD) * IND + ND + c];
    else                   v = W_hh[(size_t)(r - 2 * MD) * ND + c];
    Wcat[idx] = v;
    if (idx < CW) {
        float b;
        if (idx < MD)          b = b1[idx];
        else if (idx < 2 * MD) b = 0.f;
        else                   b = b_hh[idx - 2 * MD];
        bcat[idx] = b;
    }
}

// ---------------- precompute Wc = W_ih @ W2, bc = W_ih @ b2 ----------------
__global__ void wc_kernel(const float* __restrict__ W_ih, const float* __restrict__ W2,
                          const float* __restrict__ b2,
                          float* __restrict__ Wc, float* __restrict__ bc)
{
    int bid = blockIdx.x;
    if (bid < 96) {
        int idx = bid * 256 + threadIdx.x;
        int r = idx >> 6;
        int s = idx & 63;
        float acc = 0.f;
        #pragma unroll 8
        for (int m = 0; m < MD; m++)
            acc = fmaf(W_ih[(size_t)r * MD + m], W2[(size_t)m * MD + s], acc);
        Wc[idx] = acc;
    } else {
        for (int r = threadIdx.x; r < 3 * ND; r += blockDim.x) {
            float acc = 0.f;
            #pragma unroll 8
            for (int m = 0; m < MD; m++)
                acc = fmaf(W_ih[(size_t)r * MD + m], b2[m], acc);
            bc[r] = acc;
        }
    }
}

// ---------------- Ep precompute: Ep_ij = E_ij @ We^T (active edges only, bf16x2) ----------------
// One block per i, 8 warps; warp w handles j in [w*128, w*128+128), in chunks of 8 edges
// staged through shared memory (coalesced) to avoid uniform-LDG wavefront waste.
__global__ void ep_kernel(const float* __restrict__ E, const int* __restrict__ A,
                          const float* __restrict__ W1, unsigned* __restrict__ Ep)
{
    const int i    = blockIdx.x;
    const int tid  = threadIdx.x;
    const int w    = tid >> 5;
    const int lane = tid & 31;

    __shared__ float s_e[8][8][16];   // [warp][edge][q]

    // We rows for m = lane, lane+32
    float we0[ED], we1[ED];
    {
        const float4* p0 = (const float4*)(W1 + (size_t)lane        * IND + 2 * ND);
        const float4* p1 = (const float4*)(W1 + (size_t)(lane + 32) * IND + 2 * ND);
        #pragma unroll
        for (int q = 0; q < 4; q++) {
            float4 v = p0[q];
            we0[4*q+0] = v.x; we0[4*q+1] = v.y; we0[4*q+2] = v.z; we0[4*q+3] = v.w;
            float4 u = p1[q];
            we1[4*q+0] = u.x; we1[4*q+1] = u.y; we1[4*q+2] = u.z; we1[4*q+3] = u.w;
        }
    }

    const int jbase = w * 128;
    const int*    Arow = A + (size_t)i * NN + jbase;
    const float4* E4   = (const float4*)(E + ((size_t)i * NN + jbase) * ED);
    unsigned*     EpW  = Ep + ((size_t)i * NN + jbase) * 32;

    for (int c = 0; c < 16; c++) {          // 16 chunks x 8 edges
        // stage 8 edges (32 float4) coalesced
        ((float4*)s_e[w])[lane] = E4[c * 32 + lane];
        __syncwarp();

        int4 a0 = *(const int4*)&Arow[c * 8];
        int4 a1 = *(const int4*)&Arow[c * 8 + 4];
        int am[8] = {a0.x, a0.y, a0.z, a0.w, a1.x, a1.y, a1.z, a1.w};

        #pragma unroll
        for (int u = 0; u < 8; u++) {
            if (am[u] == 0) continue;
            const float* ep = s_e[w][u];
            float v0 = 0.f, v1 = 0.f;
            #pragma unroll
            for (int q = 0; q < ED; q++) {
                float e = ep[q];            // LDS broadcast
                v0 = fmaf(e, we0[q], v0);
                v1 = fmaf(e, we1[q], v1);
            }
            unsigned p;
            asm("cvt.rn.bf16x2.f32 %0, %1, %2;" : "=r"(p) : "f"(v1), "f"(v0));
            EpW[(size_t)(c * 8 + u) * 32 + lane] = p;
        }
        __syncwarp();
    }
}

// ---------------- GEMM: C = A @ W^T + bias + rowscale*biasd ----------------
__global__ void gemm_kernel(const float* __restrict__ A, int lda,
                            const float* __restrict__ W, int ldw,
                            const float* __restrict__ bias,
                            const float* __restrict__ biasd,
                            const float* __restrict__ rowscale,
                            float* __restrict__ C, int ldc,
                            int k)
{
    __shared__ float As[64][33];
    __shared__ float Ws[64][33];
    const int tid  = threadIdx.x;
    const int row0 = blockIdx.y * 64;
    const int col0 = blockIdx.x * 64;
    const int tr = (tid >> 4) * 4;
    const int tc = (tid & 15) * 4;

    float acc[4][4] = {};

    for (int k0 = 0; k0 < k; k0 += 32) {
        #pragma unroll
        for (int l = 0; l < 2; l++) {
            int idx = tid + l * 256;
            int r   = idx >> 3;
            int c   = (idx & 7) * 4;
            float4 av = *(const float4*)&A[(size_t)(row0 + r) * lda + k0 + c];
            As[r][c+0] = av.x; As[r][c+1] = av.y; As[r][c+2] = av.z; As[r][c+3] = av.w;
            float4 wv = *(const float4*)&W[(size_t)(col0 + r) * ldw + k0 + c];
            Ws[r][c+0] = wv.x; Ws[r][c+1] = wv.y; Ws[r][c+2] = wv.z; Ws[r][c+3] = wv.w;
        }
        __syncthreads();
        #pragma unroll
        for (int kk = 0; kk < 32; kk++) {
            float a0 = As[tr+0][kk], a1 = As[tr+1][kk], a2 = As[tr+2][kk], a3 = As[tr+3][kk];
            float b0 = Ws[tc+0][kk], b1 = Ws[tc+1][kk], b2 = Ws[tc+2][kk], b3 = Ws[tc+3][kk];
            acc[0][0] = fmaf(a0,b0,acc[0][0]); acc[0][1] = fmaf(a0,b1,acc[0][1]);
            acc[0][2] = fmaf(a0,b2,acc[0][2]); acc[0][3] = fmaf(a0,b3,acc[0][3]);
            acc[1][0] = fmaf(a1,b0,acc[1][0]); acc[1][1] = fmaf(a1,b1,acc[1][1]);
            acc[1][2] = fmaf(a1,b2,acc[1][2]); acc[1][3] = fmaf(a1,b3,acc[1][3]);
            acc[2][0] = fmaf(a2,b0,acc[2][0]); acc[2][1] = fmaf(a2,b1,acc[2][1]);
            acc[2][2] = fmaf(a2,b2,acc[2][2]); acc[2][3] = fmaf(a2,b3,acc[2][3]);
            acc[3][0] = fmaf(a3,b0,acc[3][0]); acc[3][1] = fmaf(a3,b1,acc[3][1]);
            acc[3][2] = fmaf(a3,b2,acc[3][2]); acc[3][3] = fmaf(a3,b3,acc[3][3]);
        }
        __syncthreads();
    }

    #pragma unroll
    for (int r = 0; r < 4; r++) {
        int row = row0 + tr + r;
        float rs = rowscale ? rowscale[row] : 0.0f;
        #pragma unroll
        for (int c = 0; c < 4; c++) {
            int col = col0 + tc + c;
            float v = acc[r][c];
            if (bias)  v += bias[col];
            if (biasd) v = fmaf(biasd[col], rs, v);
            C[(size_t)row * ldc + col] = v;
        }
    }
}

// ---------------- edge kernel (consumes precomputed Ep) ----------------
// S[i,:] = sum_{j: A_ij=1} relu(HB_i + HJ_j + Ep_ij)
__global__ void edge_kernel(const float* __restrict__ C,   // HB at +0, HJ at +64, ld=CW
                            const unsigned* __restrict__ Ep,
                            const int* __restrict__ A,
                            float* __restrict__ S, float* __restrict__ deg)
{
    const int i    = blockIdx.x;
    const int tid  = threadIdx.x;
    const int w    = tid >> 5;
    const int lane = tid & 31;

    __shared__ float s_sh[8][MD];
    __shared__ float d_sh[8];

    const float hb0 = C[(size_t)i * CW + lane];
    const float hb1 = C[(size_t)i * CW + lane + 32];

    float acc0 = 0.f, acc1 = 0.f;
    int dcnt = 0;

    const int       jbase = w * 128;
    const int*      Arow  = A  + (size_t)i * NN + jbase;
    const unsigned* EpW   = Ep + ((size_t)i * NN + jbase) * 32;

    for (int jj = 0; jj < 128; jj += 4) {
        int4 a4 = *(const int4*)&Arow[jj];     // warp-uniform
        #pragma unroll
        for (int u = 0; u < 4; u++) {
            int a = (u == 0) ? a4.x : (u == 1) ? a4.y : (u == 2) ? a4.z : a4.w;
            if (a == 0) continue;
            int j = jj + u;
            dcnt++;
            unsigned p = EpW[(size_t)j * 32 + lane];           // coalesced 128B
            float ep0 = __uint_as_float(p << 16);              // bf16 -> f32
            float ep1 = __uint_as_float(p & 0xFFFF0000u);
            const float* hjp = C + (size_t)(jbase + j) * CW + MD;
            float v0 = hb0 + hjp[lane]      + ep0;
            float v1 = hb1 + hjp[lane + 32] + ep1;
            acc0 += fmaxf(v0, 0.f);
            acc1 += fmaxf(v1, 0.f);
        }
    }

    s_sh[w][lane]      = acc0;
    s_sh[w][lane + 32] = acc1;
    if (lane == 0) d_sh[w] = (float)dcnt;
    __syncthreads();

    if (tid < MD) {
        float s = 0.f;
        #pragma unroll
        for (int ww = 0; ww < 8; ww++) s += s_sh[ww][tid];
        S[i * MD + tid] = s;
    }
    if (tid == MD) {
        float d = 0.f;
        #pragma unroll
        for (int ww = 0; ww < 8; ww++) d += d_sh[ww];
        deg[i] = d;
    }
}

// ---------------- elementwise GRU update ----------------
__global__ void gru_kernel(const float* __restrict__ GI, const float* __restrict__ C,
                           const float* __restrict__ Hprev, float* __restrict__ Hout)
{
    int idx = blockIdx.x * blockDim.x + threadIdx.x;   // NN*ND
    int i = idx >> 7;
    int d = idx & (ND - 1);
    const float* gi = GI + (size_t)i * 3 * ND;
    const float* gh = C + (size_t)i * CW + 2 * MD;     // GH section
    float r = 1.f / (1.f + __expf(-(gi[d]          + gh[d])));
    float z = 1.f / (1.f + __expf(-(gi[ND + d]     + gh[ND + d])));
    float narg = gi[2 * ND + d] + r * gh[2 * ND + d];
    float n = 1.f - 2.f / (__expf(2.f * narg) + 1.f);   // tanh
    float h = Hprev[idx];
    Hout[idx] = (1.f - z) * n + z * h;
}

// ---------------- launch ----------------
extern "C" void kernel_launch(void* const* d_in, const int* in_sizes, int n_in,
                              void* d_out, int out_size)
{
    const float* X    = (const float*)d_in[0];
    const int*   A    = (const int*)  d_in[1];
    const float* E    = (const float*)d_in[2];
    const float* W1   = (const float*)d_in[3];
    const float* b1   = (const float*)d_in[4];
    const float* W2   = (const float*)d_in[5];
    const float* b2   = (const float*)d_in[6];
    const float* W_ih = (const float*)d_in[7];
    const float* b_ih = (const float*)d_in[8];
    const float* W_hh = (const float*)d_in[9];
    const float* b_hh = (const float*)d_in[10];

    float *C, *S, *DEG, *GI, *H1, *H2, *Wcat, *bcat, *Wc, *bc;
    unsigned* EP;
    cudaGetSymbolAddress((void**)&C,    g_C);
    cudaGetSymbolAddress((void**)&S,    g_S);
    cudaGetSymbolAddress((void**)&DEG,  g_deg);
    cudaGetSymbolAddress((void**)&GI,   g_GI);
    cudaGetSymbolAddress((void**)&H1,   g_H1);
    cudaGetSymbolAddress((void**)&H2,   g_H2);
    cudaGetSymbolAddress((void**)&Wcat, g_Wcat);
    cudaGetSymbolAddress((void**)&bcat, g_bcat);
    cudaGetSymbolAddress((void**)&Wc,   g_Wc);
    cudaGetSymbolAddress((void**)&bc,   g_bc);
    cudaGetSymbolAddress((void**)&EP,   g_Ep);

    // one-time (per call) precomputes
    pack_kernel<<<(CW * ND) / 256, 256>>>(W1, b1, W_hh, b_hh, Wcat, bcat);
    wc_kernel<<<97, 256>>>(W_ih, W2, b2, Wc, bc);
    ep_kernel<<<NN, 256>>>(E, A, W1, EP);

    const float* Hprev = X;
    for (int t = 0; t < 3; t++) {
        float* Hout = (t == 2) ? (float*)d_out : (t == 0 ? H1 : H2);

        // C = Hprev @ Wcat^T + bcat   -> [HB | HJ | GH]
        gemm_kernel<<<dim3(CW / 64, 16), 256>>>(Hprev, ND, Wcat, ND, bcat,
                                                nullptr, nullptr, C, CW, ND);

        // masked relu-sum over edges (Ep precomputed)
        edge_kernel<<<NN, 256>>>(C, EP, A, S, DEG);

        // GI = S @ Wc^T + b_ih + deg*bc
        gemm_kernel<<<dim3((3 * ND) / 64, 16), 256>>>(S, MD, Wc, MD, b_ih,
                                                      bc, DEG, GI, 3 * ND, MD);

        // GRU update
        gru_kernel<<<(NN * ND) / 256, 256>>>(GI, C, Hprev, Hout);

        Hprev = Hout;
    }
}

// round 7
// speedup vs baseline: 1.9035x; 1.0048x over previous
#include <cuda_runtime.h>
#include <cuda_fp16.h>
#include <math.h>

#define NN   1024
#define ND   128
#define ED   16
#define MD   64
#define IND  272   // 2*ND + ED
#define CW   512   // fused pre-GEMM width: 64 (HB) + 64 (HJ) + 384 (GH)

// ---------------- scratch (no allocations allowed) ----------------
__device__ float g_C   [NN * CW];      // [HB | HJ | GH] per node
__device__ float g_S   [NN * MD];      // sum_j A_ij * relu(pre_ij)
__device__ float g_deg [NN];           // degree (float)
__device__ float g_GI  [NN * 3 * ND];
__device__ float g_H1  [NN * ND];
__device__ float g_H2  [NN * ND];
__device__ float g_Wcat[CW * ND];      // [Wi; Wj; W_hh] packed, 512 x 128
__device__ float g_bcat[CW];           // [b1; 0; b_hh]
__device__ float g_Wc  [3 * ND * MD];  // W_ih @ W2, 384 x 64
__device__ float g_bc  [3 * ND];       // W_ih @ b2
// Ep[i][j] packed fp16x2: lane u32 holds f16(ep[m=lane]) low, f16(ep[m=lane+32]) high.
__device__ unsigned g_Ep[(size_t)NN * NN * 32];   // 128 MB

// ---------------- pack kernel: build Wcat/bcat ----------------
__global__ void pack_kernel(const float* __restrict__ W1, const float* __restrict__ b1,
                            const float* __restrict__ W_hh, const float* __restrict__ b_hh,
                            float* __restrict__ Wcat, float* __restrict__ bcat)
{
    int idx = blockIdx.x * blockDim.x + threadIdx.x;
    int r = idx >> 7;
    int c = idx & 127;
    float v;
    if (r < MD)            v = W1[(size_t)r * IND + c];
    else if (r < 2 * MD)   v = W1[(size_t)(r - MD) * IND + ND + c];
    else                   v = W_hh[(size_t)(r - 2 * MD) * ND + c];
    Wcat[idx] = v;
    if (idx < CW) {
        float b;
        if (idx < MD)          b = b1[idx];
        else if (idx < 2 * MD) b = 0.f;
        else                   b = b_hh[idx - 2 * MD];
        bcat[idx] = b;
    }
}

// ---------------- precompute Wc = W_ih @ W2, bc = W_ih @ b2 ----------------
__global__ void wc_kernel(const float* __restrict__ W_ih, const float* __restrict__ W2,
                          const float* __restrict__ b2,
                          float* __restrict__ Wc, float* __restrict__ bc)
{
    int bid = blockIdx.x;
    if (bid < 96) {
        int idx = bid * 256 + threadIdx.x;
        int r = idx >> 6;
        int s = idx & 63;
        float acc = 0.f;
        #pragma unroll 8
        for (int m = 0; m < MD; m++)
            acc = fmaf(W_ih[(size_t)r * MD + m], W2[(size_t)m * MD + s], acc);
        Wc[idx] = acc;
    } else {
        for (int r = threadIdx.x; r < 3 * ND; r += blockDim.x) {
            float acc = 0.f;
            #pragma unroll 8
            for (int m = 0; m < MD; m++)
                acc = fmaf(W_ih[(size_t)r * MD + m], b2[m], acc);
            bc[r] = acc;
        }
    }
}

// ---------------- Ep precompute: Ep_ij = E_ij @ We^T (active edges only, fp16x2) ----------------
__global__ void ep_kernel(const float* __restrict__ E, const int* __restrict__ A,
                          const float* __restrict__ W1, unsigned* __restrict__ Ep)
{
    const int i    = blockIdx.x;
    const int tid  = threadIdx.x;
    const int w    = tid >> 5;
    const int lane = tid & 31;

    __shared__ float s_e[8][8][16];   // [warp][edge][q]

    // We rows for m = lane, lane+32
    float we0[ED], we1[ED];
    {
        const float4* p0 = (const float4*)(W1 + (size_t)lane        * IND + 2 * ND);
        const float4* p1 = (const float4*)(W1 + (size_t)(lane + 32) * IND + 2 * ND);
        #pragma unroll
        for (int q = 0; q < 4; q++) {
            float4 v = p0[q];
            we0[4*q+0] = v.x; we0[4*q+1] = v.y; we0[4*q+2] = v.z; we0[4*q+3] = v.w;
            float4 u = p1[q];
            we1[4*q+0] = u.x; we1[4*q+1] = u.y; we1[4*q+2] = u.z; we1[4*q+3] = u.w;
        }
    }

    const int jbase = w * 128;
    const int*    Arow = A + (size_t)i * NN + jbase;
    const float4* E4   = (const float4*)(E + ((size_t)i * NN + jbase) * ED);
    unsigned*     EpW  = Ep + ((size_t)i * NN + jbase) * 32;

    for (int c = 0; c < 16; c++) {          // 16 chunks x 8 edges
        ((float4*)s_e[w])[lane] = E4[c * 32 + lane];   // coalesced stage
        __syncwarp();

        int4 a0 = *(const int4*)&Arow[c * 8];
        int4 a1 = *(const int4*)&Arow[c * 8 + 4];
        int am[8] = {a0.x, a0.y, a0.z, a0.w, a1.x, a1.y, a1.z, a1.w};

        #pragma unroll
        for (int u = 0; u < 8; u++) {
            if (am[u] == 0) continue;
            const float* ep = s_e[w][u];
            float v0 = 0.f, v1 = 0.f;
            #pragma unroll
            for (int q = 0; q < ED; q++) {
                float e = ep[q];            // LDS broadcast
                v0 = fmaf(e, we0[q], v0);
                v1 = fmaf(e, we1[q], v1);
            }
            unsigned p;                     // fp16x2: v0 -> low, v1 -> high
            asm("cvt.rn.f16x2.f32 %0, %1, %2;" : "=r"(p) : "f"(v1), "f"(v0));
            EpW[(size_t)(c * 8 + u) * 32 + lane] = p;
        }
        __syncwarp();
    }
}

// ---------------- GEMM: C = A @ W^T + bias + rowscale*biasd ----------------
// Double-buffered smem + register prefetch; K compile-time for full unroll.
// A: n x k (lda), W: p x k (ldw), C: n x p (ldc). Grid: (p/64, n/64), 256 threads.
template<int K>
__global__ void gemm_kernel(const float* __restrict__ A, int lda,
                            const float* __restrict__ W, int ldw,
                            const float* __restrict__ bias,
                            const float* __restrict__ biasd,
                            const float* __restrict__ rowscale,
                            float* __restrict__ C, int ldc)
{
    __shared__ float As[2][64][33];
    __shared__ float Ws[2][64][33];
    constexpr int NC = K / 32;
    const int tid  = threadIdx.x;
    const int row0 = blockIdx.y * 64;
    const int col0 = blockIdx.x * 64;
    const int tr = (tid >> 4) * 4;
    const int tc = (tid & 15) * 4;
    const int lr = tid >> 3;            // 0..31 (+32 for l=1)
    const int lc = (tid & 7) * 4;       // 0..28

    float acc[4][4] = {};

    // preload chunk 0
    #pragma unroll
    for (int l = 0; l < 2; l++) {
        int r = lr + l * 32;
        float4 av = *(const float4*)&A[(size_t)(row0 + r) * lda + lc];
        As[0][r][lc+0] = av.x; As[0][r][lc+1] = av.y; As[0][r][lc+2] = av.z; As[0][r][lc+3] = av.w;
        float4 wv = *(const float4*)&W[(size_t)(col0 + r) * ldw + lc];
        Ws[0][r][lc+0] = wv.x; Ws[0][r][lc+1] = wv.y; Ws[0][r][lc+2] = wv.z; Ws[0][r][lc+3] = wv.w;
    }
    __syncthreads();

    int buf = 0;
    #pragma unroll
    for (int c0 = 0; c0 < NC; c0++) {
        float4 pa[2], pw[2];
        if (c0 + 1 < NC) {
            #pragma unroll
            for (int l = 0; l < 2; l++) {
                int r = lr + l * 32;
                pa[l] = *(const float4*)&A[(size_t)(row0 + r) * lda + (c0 + 1) * 32 + lc];
                pw[l] = *(const float4*)&W[(size_t)(col0 + r) * ldw + (c0 + 1) * 32 + lc];
            }
        }
        #pragma unroll
        for (int kk = 0; kk < 32; kk++) {
            float a0 = As[buf][tr+0][kk], a1 = As[buf][tr+1][kk],
                  a2 = As[buf][tr+2][kk], a3 = As[buf][tr+3][kk];
            float b0 = Ws[buf][tc+0][kk], b1 = Ws[buf][tc+1][kk],
                  b2 = Ws[buf][tc+2][kk], b3 = Ws[buf][tc+3][kk];
            acc[0][0] = fmaf(a0,b0,acc[0][0]); acc[0][1] = fmaf(a0,b1,acc[0][1]);
            acc[0][2] = fmaf(a0,b2,acc[0][2]); acc[0][3] = fmaf(a0,b3,acc[0][3]);
            acc[1][0] = fmaf(a1,b0,acc[1][0]); acc[1][1] = fmaf(a1,b1,acc[1][1]);
            acc[1][2] = fmaf(a1,b2,acc[1][2]); acc[1][3] = fmaf(a1,b3,acc[1][3]);
            acc[2][0] = fmaf(a2,b0,acc[2][0]); acc[2][1] = fmaf(a2,b1,acc[2][1]);
            acc[2][2] = fmaf(a2,b2,acc[2][2]); acc[2][3] = fmaf(a2,b3,acc[2][3]);
            acc[3][0] = fmaf(a3,b0,acc[3][0]); acc[3][1] = fmaf(a3,b1,acc[3][1]);
            acc[3][2] = fmaf(a3,b2,acc[3][2]); acc[3][3] = fmaf(a3,b3,acc[3][3]);
        }
        if (c0 + 1 < NC) {
            // buf^1 readers finished before the sync that preceded this chunk
            #pragma unroll
            for (int l = 0; l < 2; l++) {
                int r = lr + l * 32;
                As[buf^1][r][lc+0] = pa[l].x; As[buf^1][r][lc+1] = pa[l].y;
                As[buf^1][r][lc+2] = pa[l].z; As[buf^1][r][lc+3] = pa[l].w;
                Ws[buf^1][r][lc+0] = pw[l].x; Ws[buf^1][r][lc+1] = pw[l].y;
                Ws[buf^1][r][lc+2] = pw[l].z; Ws[buf^1][r][lc+3] = pw[l].w;
            }
            __syncthreads();
            buf ^= 1;
        }
    }

    #pragma unroll
    for (int r = 0; r < 4; r++) {
        int row = row0 + tr + r;
        float rs = rowscale ? rowscale[row] : 0.0f;
        #pragma unroll
        for (int c = 0; c < 4; c++) {
            int col = col0 + tc + c;
            float v = acc[r][c];
            if (bias)  v += bias[col];
            if (biasd) v = fmaf(biasd[col], rs, v);
            C[(size_t)row * ldc + col] = v;
        }
    }
}

// ---------------- edge kernel (consumes precomputed Ep, fp16x2) ----------------
// S[i,:] = sum_{j: A_ij=1} relu(HB_i + HJ_j + Ep_ij)
__global__ void edge_kernel(const float* __restrict__ C,   // HB at +0, HJ at +64, ld=CW
                            const unsigned* __restrict__ Ep,
                            const int* __restrict__ A,
                            float* __restrict__ S, float* __restrict__ deg)
{
    const int i    = blockIdx.x;
    const int tid  = threadIdx.x;
    const int w    = tid >> 5;
    const int lane = tid & 31;

    __shared__ float s_sh[8][MD];
    __shared__ float d_sh[8];

    const float hb0 = C[(size_t)i * CW + lane];
    const float hb1 = C[(size_t)i * CW + lane + 32];

    float acc0 = 0.f, acc1 = 0.f;
    int dcnt = 0;

    const int       jbase = w * 128;
    const int*      Arow  = A  + (size_t)i * NN + jbase;
    const unsigned* EpW   = Ep + ((size_t)i * NN + jbase) * 32;

    for (int jj = 0; jj < 128; jj += 4) {
        int4 a4 = *(const int4*)&Arow[jj];     // warp-uniform
        #pragma unroll
        for (int u = 0; u < 4; u++) {
            int a = (u == 0) ? a4.x : (u == 1) ? a4.y : (u == 2) ? a4.z : a4.w;
            if (a == 0) continue;
            int j = jj + u;
            dcnt++;
            unsigned p = EpW[(size_t)j * 32 + lane];           // coalesced 128B
            __half2 h = *reinterpret_cast<const __half2*>(&p);
            float2 ef = __half22float2(h);                     // .x = m=lane, .y = m=lane+32
            const float* hjp = C + (size_t)(jbase + j) * CW + MD;
            float v0 = hb0 + hjp[lane]      + ef.x;
            float v1 = hb1 + hjp[lane + 32] + ef.y;
            acc0 += fmaxf(v0, 0.f);
            acc1 += fmaxf(v1, 0.f);
        }
    }

    s_sh[w][lane]      = acc0;
    s_sh[w][lane + 32] = acc1;
    if (lane == 0) d_sh[w] = (float)dcnt;
    __syncthreads();

    if (tid < MD) {
        float s = 0.f;
        #pragma unroll
        for (int ww = 0; ww < 8; ww++) s += s_sh[ww][tid];
        S[i * MD + tid] = s;
    }
    if (tid == MD) {
        float d = 0.f;
        #pragma unroll
        for (int ww = 0; ww < 8; ww++) d += d_sh[ww];
        deg[i] = d;
    }
}

// ---------------- elementwise GRU update ----------------
__global__ void gru_kernel(const float* __restrict__ GI, const float* __restrict__ C,
                           const float* __restrict__ Hprev, float* __restrict__ Hout)
{
    int idx = blockIdx.x * blockDim.x + threadIdx.x;   // NN*ND
    int i = idx >> 7;
    int d = idx & (ND - 1);
    const float* gi = GI + (size_t)i * 3 * ND;
    const float* gh = C + (size_t)i * CW + 2 * MD;     // GH section
    float r = 1.f / (1.f + __expf(-(gi[d]          + gh[d])));
    float z = 1.f / (1.f + __expf(-(gi[ND + d]     + gh[ND + d])));
    float narg = gi[2 * ND + d] + r * gh[2 * ND + d];
    float n = 1.f - 2.f / (__expf(2.f * narg) + 1.f);   // tanh
    float h = Hprev[idx];
    Hout[idx] = (1.f - z) * n + z * h;
}

// ---------------- launch ----------------
extern "C" void kernel_launch(void* const* d_in, const int* in_sizes, int n_in,
                              void* d_out, int out_size)
{
    const float* X    = (const float*)d_in[0];
    const int*   A    = (const int*)  d_in[1];
    const float* E    = (const float*)d_in[2];
    const float* W1   = (const float*)d_in[3];
    const float* b1   = (const float*)d_in[4];
    const float* W2   = (const float*)d_in[5];
    const float* b2   = (const float*)d_in[6];
    const float* W_ih = (const float*)d_in[7];
    const float* b_ih = (const float*)d_in[8];
    const float* W_hh = (const float*)d_in[9];
    const float* b_hh = (const float*)d_in[10];

    float *C, *S, *DEG, *GI, *H1, *H2, *Wcat, *bcat, *Wc, *bc;
    unsigned* EP;
    cudaGetSymbolAddress((void**)&C,    g_C);
    cudaGetSymbolAddress((void**)&S,    g_S);
    cudaGetSymbolAddress((void**)&DEG,  g_deg);
    cudaGetSymbolAddress((void**)&GI,   g_GI);
    cudaGetSymbolAddress((void**)&H1,   g_H1);
    cudaGetSymbolAddress((void**)&H2,   g_H2);
    cudaGetSymbolAddress((void**)&Wcat, g_Wcat);
    cudaGetSymbolAddress((void**)&bcat, g_bcat);
    cudaGetSymbolAddress((void**)&Wc,   g_Wc);
    cudaGetSymbolAddress((void**)&bc,   g_bc);
    cudaGetSymbolAddress((void**)&EP,   g_Ep);

    // one-time (per call) precomputes
    pack_kernel<<<(CW * ND) / 256, 256>>>(W1, b1, W_hh, b_hh, Wcat, bcat);
    wc_kernel<<<97, 256>>>(W_ih, W2, b2, Wc, bc);
    ep_kernel<<<NN, 256>>>(E, A, W1, EP);

    const float* Hprev = X;
    for (int t = 0; t < 3; t++) {
        float* Hout = (t == 2) ? (float*)d_out : (t == 0 ? H1 : H2);

        // C = Hprev @ Wcat^T + bcat   -> [HB | HJ | GH]
        gemm_kernel<128><<<dim3(CW / 64, 16), 256>>>(Hprev, ND, Wcat, ND, bcat,
                                                     nullptr, nullptr, C, CW);

        // masked relu-sum over edges (Ep precomputed)
        edge_kernel<<<NN, 256>>>(C, EP, A, S, DEG);

        // GI = S @ Wc^T + b_ih + deg*bc
        gemm_kernel<64><<<dim3((3 * ND) / 64, 16), 256>>>(S, MD, Wc, MD, b_ih,
                                                          bc, DEG, GI, 3 * ND);

        // GRU update
        gru_kernel<<<(NN * ND) / 256, 256>>>(GI, C, Hprev, Hout);

        Hprev = Hout;
    }
}

// round 8
// speedup vs baseline: 1.9358x; 1.0170x over previous
#include <cuda_runtime.h>
#include <cuda_fp16.h>
#include <math.h>

#define NN   1024
#define ND   128
#define ED   16
#define MD   64
#define IND  272   // 2*ND + ED
#define CW   512   // fused pre-GEMM width: 64 (HB) + 64 (HJ) + 384 (GH)

// ---------------- scratch (no allocations allowed) ----------------
// C row layout: [HB interleaved (64) | HJ interleaved (64) | GH (384)]
// "interleaved": col 2m = unit m, col 2m+1 = unit m+32  (m in 0..31)
__device__ float g_C   [NN * CW];
__device__ float g_S   [NN * MD];      // sum_j A_ij * relu(pre_ij)
__device__ float g_deg [NN];           // degree (float)
__device__ float g_GI  [NN * 3 * ND];
__device__ float g_H1  [NN * ND];
__device__ float g_H2  [NN * ND];
__device__ float g_Wcat[CW * ND];      // permuted [Wi; Wj; W_hh], 512 x 128
__device__ float g_bcat[CW];           // [b1 perm; 0; b_hh]
__device__ float g_Wc  [3 * ND * MD];  // W_ih @ W2, 384 x 64
__device__ float g_bc  [3 * ND];       // W_ih @ b2
// Ep[i][j] packed fp16x2: lane u32 = f16(ep[m=lane]) low, f16(ep[m=lane+32]) high.
__device__ unsigned g_Ep[(size_t)NN * NN * 32];   // 128 MB

// ---------------- pack kernel: build Wcat/bcat (HB/HJ rows interleaved) ----------------
__global__ void pack_kernel(const float* __restrict__ W1, const float* __restrict__ b1,
                            const float* __restrict__ W_hh, const float* __restrict__ b_hh,
                            float* __restrict__ Wcat, float* __restrict__ bcat)
{
    int idx = blockIdx.x * blockDim.x + threadIdx.x;
    int r = idx >> 7;
    int c = idx & 127;
    float v;
    if (r < MD) {                       // HB section: interleaved Wi rows
        int m = (r >> 1) + ((r & 1) << 5);     // r even -> r/2, odd -> r/2+32
        v = W1[(size_t)m * IND + c];
    } else if (r < 2 * MD) {            // HJ section: interleaved Wj rows
        int rr = r - MD;
        int m = (rr >> 1) + ((rr & 1) << 5);
        v = W1[(size_t)m * IND + ND + c];
    } else {
        v = W_hh[(size_t)(r - 2 * MD) * ND + c];
    }
    Wcat[idx] = v;
    if (idx < CW) {
        float b;
        if (idx < MD) {
            int m = (idx >> 1) + ((idx & 1) << 5);
            b = b1[m];
        }
        else if (idx < 2 * MD) b = 0.f;
        else                   b = b_hh[idx - 2 * MD];
        bcat[idx] = b;
    }
}

// ---------------- precompute Wc = W_ih @ W2, bc = W_ih @ b2 ----------------
__global__ void wc_kernel(const float* __restrict__ W_ih, const float* __restrict__ W2,
                          const float* __restrict__ b2,
                          float* __restrict__ Wc, float* __restrict__ bc)
{
    int bid = blockIdx.x;
    if (bid < 96) {
        int idx = bid * 256 + threadIdx.x;
        int r = idx >> 6;
        int s = idx & 63;
        float acc = 0.f;
        #pragma unroll 8
        for (int m = 0; m < MD; m++)
            acc = fmaf(W_ih[(size_t)r * MD + m], W2[(size_t)m * MD + s], acc);
        Wc[idx] = acc;
    } else {
        for (int r = threadIdx.x; r < 3 * ND; r += blockDim.x) {
            float acc = 0.f;
            #pragma unroll 8
            for (int m = 0; m < MD; m++)
                acc = fmaf(W_ih[(size_t)r * MD + m], b2[m], acc);
            bc[r] = acc;
        }
    }
}

// ---------------- Ep precompute: Ep_ij = E_ij @ We^T (active edges only, fp16x2) ----------------
__global__ void ep_kernel(const float* __restrict__ E, const int* __restrict__ A,
                          const float* __restrict__ W1, unsigned* __restrict__ Ep)
{
    const int i    = blockIdx.x;
    const int tid  = threadIdx.x;
    const int w    = tid >> 5;
    const int lane = tid & 31;

    __shared__ float s_e[8][8][16];   // [warp][edge][q]

    float we0[ED], we1[ED];
    {
        const float4* p0 = (const float4*)(W1 + (size_t)lane        * IND + 2 * ND);
        const float4* p1 = (const float4*)(W1 + (size_t)(lane + 32) * IND + 2 * ND);
        #pragma unroll
        for (int q = 0; q < 4; q++) {
            float4 v = p0[q];
            we0[4*q+0] = v.x; we0[4*q+1] = v.y; we0[4*q+2] = v.z; we0[4*q+3] = v.w;
            float4 u = p1[q];
            we1[4*q+0] = u.x; we1[4*q+1] = u.y; we1[4*q+2] = u.z; we1[4*q+3] = u.w;
        }
    }

    const int jbase = w * 128;
    const int*    Arow = A + (size_t)i * NN + jbase;
    const float4* E4   = (const float4*)(E + ((size_t)i * NN + jbase) * ED);
    unsigned*     EpW  = Ep + ((size_t)i * NN + jbase) * 32;

    for (int c = 0; c < 16; c++) {          // 16 chunks x 8 edges
        ((float4*)s_e[w])[lane] = E4[c * 32 + lane];   // coalesced stage
        __syncwarp();

        int4 a0 = *(const int4*)&Arow[c * 8];
        int4 a1 = *(const int4*)&Arow[c * 8 + 4];
        int am[8] = {a0.x, a0.y, a0.z, a0.w, a1.x, a1.y, a1.z, a1.w};

        #pragma unroll
        for (int u = 0; u < 8; u++) {
            if (am[u] == 0) continue;
            const float* ep = s_e[w][u];
            float v0 = 0.f, v1 = 0.f;
            #pragma unroll
            for (int q = 0; q < ED; q++) {
                float e = ep[q];            // LDS broadcast
                v0 = fmaf(e, we0[q], v0);
                v1 = fmaf(e, we1[q], v1);
            }
            unsigned p;                     // fp16x2: v0 -> low, v1 -> high
            asm("cvt.rn.f16x2.f32 %0, %1, %2;" : "=r"(p) : "f"(v1), "f"(v0));
            EpW[(size_t)(c * 8 + u) * 32 + lane] = p;
        }
        __syncwarp();
    }
}

// ---------------- GEMM: C = A @ W^T + bias + rowscale*biasd ----------------
// 64x32 output tile, 256 threads, 4x2 micro-tile, double-buffered smem.
// A: n x k (lda), W: p x k (ldw), C: n x p (ldc). Grid: (p/32, n/64).
template<int K>
__global__ void gemm_kernel(const float* __restrict__ A, int lda,
                            const float* __restrict__ W, int ldw,
                            const float* __restrict__ bias,
                            const float* __restrict__ biasd,
                            const float* __restrict__ rowscale,
                            float* __restrict__ C, int ldc)
{
    __shared__ float As[2][64][33];
    __shared__ float Ws[2][32][33];
    constexpr int NC = K / 32;
    const int tid  = threadIdx.x;
    const int row0 = blockIdx.y * 64;
    const int col0 = blockIdx.x * 32;
    const int tr = (tid >> 4) * 4;      // 16 groups x 4 rows
    const int tc = (tid & 15) * 2;      // 16 groups x 2 cols
    const int ar = tid >> 3;            // A loader: 0..31 (+32)
    const int ac = (tid & 7) * 4;
    const int wr = tid >> 3;            // W loader: 0..31 (first 256 slots)
    const int wc = (tid & 7) * 4;

    float acc[4][2] = {};

    // preload chunk 0
    #pragma unroll
    for (int l = 0; l < 2; l++) {
        int r = ar + l * 32;
        float4 av = *(const float4*)&A[(size_t)(row0 + r) * lda + ac];
        As[0][r][ac+0] = av.x; As[0][r][ac+1] = av.y; As[0][r][ac+2] = av.z; As[0][r][ac+3] = av.w;
    }
    {
        float4 wv = *(const float4*)&W[(size_t)(col0 + wr) * ldw + wc];
        Ws[0][wr][wc+0] = wv.x; Ws[0][wr][wc+1] = wv.y; Ws[0][wr][wc+2] = wv.z; Ws[0][wr][wc+3] = wv.w;
    }
    __syncthreads();

    int buf = 0;
    #pragma unroll
    for (int c0 = 0; c0 < NC; c0++) {
        float4 pa[2], pw;
        if (c0 + 1 < NC) {
            #pragma unroll
            for (int l = 0; l < 2; l++) {
                int r = ar + l * 32;
                pa[l] = *(const float4*)&A[(size_t)(row0 + r) * lda + (c0 + 1) * 32 + ac];
            }
            pw = *(const float4*)&W[(size_t)(col0 + wr) * ldw + (c0 + 1) * 32 + wc];
        }
        #pragma unroll
        for (int kk = 0; kk < 32; kk++) {
            float a0 = As[buf][tr+0][kk], a1 = As[buf][tr+1][kk],
                  a2 = As[buf][tr+2][kk], a3 = As[buf][tr+3][kk];
            float b0 = Ws[buf][tc+0][kk], b1 = Ws[buf][tc+1][kk];
            acc[0][0] = fmaf(a0,b0,acc[0][0]); acc[0][1] = fmaf(a0,b1,acc[0][1]);
            acc[1][0] = fmaf(a1,b0,acc[1][0]); acc[1][1] = fmaf(a1,b1,acc[1][1]);
            acc[2][0] = fmaf(a2,b0,acc[2][0]); acc[2][1] = fmaf(a2,b1,acc[2][1]);
            acc[3][0] = fmaf(a3,b0,acc[3][0]); acc[3][1] = fmaf(a3,b1,acc[3][1]);
        }
        if (c0 + 1 < NC) {
            #pragma unroll
            for (int l = 0; l < 2; l++) {
                int r = ar + l * 32;
                As[buf^1][r][ac+0] = pa[l].x; As[buf^1][r][ac+1] = pa[l].y;
                As[buf^1][r][ac+2] = pa[l].z; As[buf^1][r][ac+3] = pa[l].w;
            }
            Ws[buf^1][wr][wc+0] = pw.x; Ws[buf^1][wr][wc+1] = pw.y;
            Ws[buf^1][wr][wc+2] = pw.z; Ws[buf^1][wr][wc+3] = pw.w;
            __syncthreads();
            buf ^= 1;
        }
    }

    #pragma unroll
    for (int r = 0; r < 4; r++) {
        int row = row0 + tr + r;
        float rs = rowscale ? rowscale[row] : 0.0f;
        #pragma unroll
        for (int c = 0; c < 2; c++) {
            int col = col0 + tc + c;
            float v = acc[r][c];
            if (bias)  v += bias[col];
            if (biasd) v = fmaf(biasd[col], rs, v);
            C[(size_t)row * ldc + col] = v;
        }
    }
}

// ---------------- edge kernel (Ep fp16x2 + interleaved HJ: 2 LDG/edge) ----------------
// S[i,:] = sum_{j: A_ij=1} relu(HB_i + HJ_j + Ep_ij)
__global__ void edge_kernel(const float* __restrict__ C,   // HBint at +0, HJint at +64
                            const unsigned* __restrict__ Ep,
                            const int* __restrict__ A,
                            float* __restrict__ S, float* __restrict__ deg)
{
    const int i    = blockIdx.x;
    const int tid  = threadIdx.x;
    const int w    = tid >> 5;
    const int lane = tid & 31;

    __shared__ float s_sh[8][MD];
    __shared__ float d_sh[8];

    const float2 hb2 = *(const float2*)(C + (size_t)i * CW + 2 * lane);

    float acc0 = 0.f, acc1 = 0.f;
    int dcnt = 0;

    const int       jbase = w * 128;
    const int*      Arow  = A  + (size_t)i * NN + jbase;
    const unsigned* EpW   = Ep + ((size_t)i * NN + jbase) * 32;

    for (int jj = 0; jj < 128; jj += 4) {
        int4 a4 = *(const int4*)&Arow[jj];     // warp-uniform
        #pragma unroll
        for (int u = 0; u < 4; u++) {
            int a = (u == 0) ? a4.x : (u == 1) ? a4.y : (u == 2) ? a4.z : a4.w;
            if (a == 0) continue;
            int j = jj + u;
            dcnt++;
            unsigned p = EpW[(size_t)j * 32 + lane];                   // 1 LDG.32
            __half2 h = *reinterpret_cast<const __half2*>(&p);
            float2 ef = __half22float2(h);                             // .x=m, .y=m+32
            float2 hj = *(const float2*)(C + (size_t)(jbase + j) * CW + MD + 2 * lane); // 1 LDG.64
            float v0 = hb2.x + hj.x + ef.x;
            float v1 = hb2.y + hj.y + ef.y;
            acc0 += fmaxf(v0, 0.f);
            acc1 += fmaxf(v1, 0.f);
        }
    }

    s_sh[w][lane]      = acc0;   // m = lane
    s_sh[w][lane + 32] = acc1;   // m = lane + 32
    if (lane == 0) d_sh[w] = (float)dcnt;
    __syncthreads();

    if (tid < MD) {
        float s = 0.f;
        #pragma unroll
        for (int ww = 0; ww < 8; ww++) s += s_sh[ww][tid];
        S[i * MD + tid] = s;
    }
    if (tid == MD) {
        float d = 0.f;
        #pragma unroll
        for (int ww = 0; ww < 8; ww++) d += d_sh[ww];
        deg[i] = d;
    }
}

// ---------------- elementwise GRU update ----------------
__global__ void gru_kernel(const float* __restrict__ GI, const float* __restrict__ C,
                           const float* __restrict__ Hprev, float* __restrict__ Hout)
{
    int idx = blockIdx.x * blockDim.x + threadIdx.x;   // NN*ND
    int i = idx >> 7;
    int d = idx & (ND - 1);
    const float* gi = GI + (size_t)i * 3 * ND;
    const float* gh = C + (size_t)i * CW + 2 * MD;     // GH section (unpermuted)
    float r = 1.f / (1.f + __expf(-(gi[d]          + gh[d])));
    float z = 1.f / (1.f + __expf(-(gi[ND + d]     + gh[ND + d])));
    float narg = gi[2 * ND + d] + r * gh[2 * ND + d];
    float n = 1.f - 2.f / (__expf(2.f * narg) + 1.f);   // tanh
    float h = Hprev[idx];
    Hout[idx] = (1.f - z) * n + z * h;
}

// ---------------- launch ----------------
extern "C" void kernel_launch(void* const* d_in, const int* in_sizes, int n_in,
                              void* d_out, int out_size)
{
    const float* X    = (const float*)d_in[0];
    const int*   A    = (const int*)  d_in[1];
    const float* E    = (const float*)d_in[2];
    const float* W1   = (const float*)d_in[3];
    const float* b1   = (const float*)d_in[4];
    const float* W2   = (const float*)d_in[5];
    const float* b2   = (const float*)d_in[6];
    const float* W_ih = (const float*)d_in[7];
    const float* b_ih = (const float*)d_in[8];
    const float* W_hh = (const float*)d_in[9];
    const float* b_hh = (const float*)d_in[10];

    float *C, *S, *DEG, *GI, *H1, *H2, *Wcat, *bcat, *Wc, *bc;
    unsigned* EP;
    cudaGetSymbolAddress((void**)&C,    g_C);
    cudaGetSymbolAddress((void**)&S,    g_S);
    cudaGetSymbolAddress((void**)&DEG,  g_deg);
    cudaGetSymbolAddress((void**)&GI,   g_GI);
    cudaGetSymbolAddress((void**)&H1,   g_H1);
    cudaGetSymbolAddress((void**)&H2,   g_H2);
    cudaGetSymbolAddress((void**)&Wcat, g_Wcat);
    cudaGetSymbolAddress((void**)&bcat, g_bcat);
    cudaGetSymbolAddress((void**)&Wc,   g_Wc);
    cudaGetSymbolAddress((void**)&bc,   g_bc);
    cudaGetSymbolAddress((void**)&EP,   g_Ep);

    // one-time (per call) precomputes
    pack_kernel<<<(CW * ND) / 256, 256>>>(W1, b1, W_hh, b_hh, Wcat, bcat);
    wc_kernel<<<97, 256>>>(W_ih, W2, b2, Wc, bc);
    ep_kernel<<<NN, 256>>>(E, A, W1, EP);

    const float* Hprev = X;
    for (int t = 0; t < 3; t++) {
        float* Hout = (t == 2) ? (float*)d_out : (t == 0 ? H1 : H2);

        // C = Hprev @ Wcat^T + bcat   -> [HBint | HJint | GH]
        gemm_kernel<128><<<dim3(CW / 32, 16), 256>>>(Hprev, ND, Wcat, ND, bcat,
                                                     nullptr, nullptr, C, CW);

        // masked relu-sum over edges (Ep precomputed)
        edge_kernel<<<NN, 256>>>(C, EP, A, S, DEG);

        // GI = S @ Wc^T + b_ih + deg*bc
        gemm_kernel<64><<<dim3((3 * ND) / 32, 16), 256>>>(S, MD, Wc, MD, b_ih,
                                                          bc, DEG, GI, 3 * ND);

        // GRU update
        gru_kernel<<<(NN * ND) / 256, 256>>>(GI, C, Hprev, Hout);

        Hprev = Hout;
    }
}

// round 9
// speedup vs baseline: 1.9828x; 1.0242x over previous
#include <cuda_runtime.h>
#include <cuda_fp16.h>
#include <math.h>

#define NN   1024
#define ND   128
#define ED   16
#define MD   64
#define IND  272   // 2*ND + ED
#define CW   512   // fused pre-GEMM width: 64 (HBint) + 64 (HJint) + 384 (GH)

// ---------------- scratch (no allocations allowed) ----------------
__device__ float g_C   [NN * CW];
__device__ float g_S   [NN * MD];
__device__ float g_deg [NN];           // degree (float, iteration-invariant)
__device__ int   g_idg [NN];           // degree (int)
__device__ int   g_off [NN];           // CSR row offsets (padded to 4)
__device__ float g_GI  [NN * 3 * ND];
__device__ float g_H1  [NN * ND];
__device__ float g_H2  [NN * ND];
__device__ float g_Wcat[CW * ND];
__device__ float g_bcat[CW];
__device__ float g_Wc  [3 * ND * MD];  // W_ih @ W2
__device__ float g_bc  [3 * ND];       // W_ih @ b2
// Compacted Ep: edge e (global CSR position) -> 32 u32 (fp16x2 per lane: m, m+32)
__device__ unsigned       g_EpC [(size_t)NN * NN * 32 + (size_t)4 * NN * 32];
__device__ unsigned short g_Jidx[(size_t)NN * NN + 4 * NN + 8];

// ---------------- pack kernel: build Wcat/bcat (HB/HJ rows interleaved) ----------------
__global__ void pack_kernel(const float* __restrict__ W1, const float* __restrict__ b1,
                            const float* __restrict__ W_hh, const float* __restrict__ b_hh,
                            float* __restrict__ Wcat, float* __restrict__ bcat)
{
    int idx = blockIdx.x * blockDim.x + threadIdx.x;
    int r = idx >> 7;
    int c = idx & 127;
    float v;
    if (r < MD) {                       // HB section: interleaved Wi rows
        int m = (r >> 1) + ((r & 1) << 5);
        v = W1[(size_t)m * IND + c];
    } else if (r < 2 * MD) {            // HJ section: interleaved Wj rows
        int rr = r - MD;
        int m = (rr >> 1) + ((rr & 1) << 5);
        v = W1[(size_t)m * IND + ND + c];
    } else {
        v = W_hh[(size_t)(r - 2 * MD) * ND + c];
    }
    Wcat[idx] = v;
    if (idx < CW) {
        float b;
        if (idx < MD) {
            int m = (idx >> 1) + ((idx & 1) << 5);
            b = b1[m];
        }
        else if (idx < 2 * MD) b = 0.f;
        else                   b = b_hh[idx - 2 * MD];
        bcat[idx] = b;
    }
}

// ---------------- precompute Wc = W_ih @ W2, bc = W_ih @ b2 ----------------
__global__ void wc_kernel(const float* __restrict__ W_ih, const float* __restrict__ W2,
                          const float* __restrict__ b2,
                          float* __restrict__ Wc, float* __restrict__ bc)
{
    int bid = blockIdx.x;
    if (bid < 96) {
        int idx = bid * 256 + threadIdx.x;
        int r = idx >> 6;
        int s = idx & 63;
        float acc = 0.f;
        #pragma unroll 8
        for (int m = 0; m < MD; m++)
            acc = fmaf(W_ih[(size_t)r * MD + m], W2[(size_t)m * MD + s], acc);
        Wc[idx] = acc;
    } else {
        for (int r = threadIdx.x; r < 3 * ND; r += blockDim.x) {
            float acc = 0.f;
            #pragma unroll 8
            for (int m = 0; m < MD; m++)
                acc = fmaf(W_ih[(size_t)r * MD + m], b2[m], acc);
            bc[r] = acc;
        }
    }
}

// ---------------- degree kernel: one warp per row ----------------
__global__ void deg_kernel(const int* __restrict__ A, int* __restrict__ idg,
                           float* __restrict__ deg)
{
    int gtid = blockIdx.x * blockDim.x + threadIdx.x;
    int row  = gtid >> 5;
    int lane = gtid & 31;
    if (row >= NN) return;
    const int4* Arow = (const int4*)(A + (size_t)row * NN);
    int s = 0;
    #pragma unroll
    for (int q = 0; q < 8; q++) {
        int4 v = Arow[lane + q * 32];
        s += v.x + v.y + v.z + v.w;
    }
    #pragma unroll
    for (int o = 16; o; o >>= 1) s += __shfl_xor_sync(0xffffffffu, s, o);
    if (lane == 0) { idg[row] = s; deg[row] = (float)s; }
}

// ---------------- scan kernel: exclusive prefix of padded degrees ----------------
__global__ void scan_kernel(const int* __restrict__ idg, int* __restrict__ off)
{
    __shared__ int sm[NN];
    int tid = threadIdx.x;
    int pad = (idg[tid] + 3) & ~3;     // pad row length to multiple of 4
    sm[tid] = pad;
    __syncthreads();
    for (int o = 1; o < NN; o <<= 1) {
        int v = (tid >= o) ? sm[tid - o] : 0;
        __syncthreads();
        sm[tid] += v;
        __syncthreads();
    }
    off[tid] = sm[tid] - pad;          // exclusive
}

// ---------------- Ep precompute: compacted CSR write ----------------
__global__ void ep_kernel(const float* __restrict__ E, const int* __restrict__ A,
                          const float* __restrict__ W1, const int* __restrict__ off,
                          unsigned* __restrict__ EpC, unsigned short* __restrict__ Jidx)
{
    const int i    = blockIdx.x;
    const int tid  = threadIdx.x;
    const int w    = tid >> 5;
    const int lane = tid & 31;

    __shared__ float s_e[8][8][16];   // [warp][edge][q]
    __shared__ int   wcnt[8];

    // We rows for m = lane, lane+32
    float we0[ED], we1[ED];
    {
        const float4* p0 = (const float4*)(W1 + (size_t)lane        * IND + 2 * ND);
        const float4* p1 = (const float4*)(W1 + (size_t)(lane + 32) * IND + 2 * ND);
        #pragma unroll
        for (int q = 0; q < 4; q++) {
            float4 v = p0[q];
            we0[4*q+0] = v.x; we0[4*q+1] = v.y; we0[4*q+2] = v.z; we0[4*q+3] = v.w;
            float4 u = p1[q];
            we1[4*q+0] = u.x; we1[4*q+1] = u.y; we1[4*q+2] = u.z; we1[4*q+3] = u.w;
        }
    }

    const int jbase = w * 128;
    const int* Arow = A + (size_t)i * NN + jbase;

    // ballot masks for this warp's 128 j's
    unsigned bal[4];
    int myact = 0;
    #pragma unroll
    for (int s = 0; s < 4; s++) {
        int a = Arow[s * 32 + lane];
        bal[s] = __ballot_sync(0xffffffffu, a != 0);
        myact += __popc(bal[s]);
    }
    if (lane == 0) wcnt[w] = myact;
    __syncthreads();
    int pos = off[i];
    for (int ww = 0; ww < w; ww++) pos += wcnt[ww];

    const float4* E4 = (const float4*)(E + ((size_t)i * NN + jbase) * ED);

    for (int c = 0; c < 16; c++) {          // 16 chunks x 8 edges
        ((float4*)s_e[w])[lane] = E4[c * 32 + lane];   // coalesced stage
        __syncwarp();
        #pragma unroll
        for (int u = 0; u < 8; u++) {
            int jloc = c * 8 + u;
            if (!((bal[jloc >> 5] >> (jloc & 31)) & 1u)) continue;
            const float* ep = s_e[w][u];
            float v0 = 0.f, v1 = 0.f;
            #pragma unroll
            for (int q = 0; q < ED; q++) {
                float e = ep[q];
                v0 = fmaf(e, we0[q], v0);
                v1 = fmaf(e, we1[q], v1);
            }
            unsigned p;
            asm("cvt.rn.f16x2.f32 %0, %1, %2;" : "=r"(p) : "f"(v1), "f"(v0));
            EpC[(size_t)pos * 32 + lane] = p;
            if (lane == 0) Jidx[pos] = (unsigned short)(jbase + jloc);
            pos++;
        }
        __syncwarp();
    }
}

// ---------------- GEMM: C = A @ W^T + bias + rowscale*biasd ----------------
// 64x32 tile, 256 threads, 4x2 micro; smem transposed [k][row] -> LDS.128/LDS.64.
template<int K>
__global__ void gemm_kernel(const float* __restrict__ A, int lda,
                            const float* __restrict__ W, int ldw,
                            const float* __restrict__ bias,
                            const float* __restrict__ biasd,
                            const float* __restrict__ rowscale,
                            float* __restrict__ C, int ldc)
{
    __shared__ float As[2][32][68];     // [buf][kk][row], stride 68*4B keeps 16B align
    __shared__ float Ws[2][32][36];     // [buf][kk][col], stride 36*4B keeps 8B align
    constexpr int NC = K / 32;
    const int tid  = threadIdx.x;
    const int row0 = blockIdx.y * 64;
    const int col0 = blockIdx.x * 32;
    const int tr = (tid >> 4) * 4;      // 0..60
    const int tc = (tid & 15) * 2;      // 0..30
    const int ar = tid >> 3;            // 0..31
    const int ac = (tid & 7) * 4;       // 0..28

    float acc[4][2] = {};

    // preload chunk 0
    #pragma unroll
    for (int l = 0; l < 2; l++) {
        int r = ar + l * 32;
        float4 av = *(const float4*)&A[(size_t)(row0 + r) * lda + ac];
        As[0][ac+0][r] = av.x; As[0][ac+1][r] = av.y;
        As[0][ac+2][r] = av.z; As[0][ac+3][r] = av.w;
    }
    {
        float4 wv = *(const float4*)&W[(size_t)(col0 + ar) * ldw + ac];
        Ws[0][ac+0][ar] = wv.x; Ws[0][ac+1][ar] = wv.y;
        Ws[0][ac+2][ar] = wv.z; Ws[0][ac+3][ar] = wv.w;
    }
    __syncthreads();

    int buf = 0;
    #pragma unroll
    for (int c0 = 0; c0 < NC; c0++) {
        float4 pa[2], pw;
        if (c0 + 1 < NC) {
            #pragma unroll
            for (int l = 0; l < 2; l++) {
                int r = ar + l * 32;
                pa[l] = *(const float4*)&A[(size_t)(row0 + r) * lda + (c0 + 1) * 32 + ac];
            }
            pw = *(const float4*)&W[(size_t)(col0 + ar) * ldw + (c0 + 1) * 32 + ac];
        }
        #pragma unroll
        for (int kk = 0; kk < 32; kk++) {
            float4 a4 = *(const float4*)&As[buf][kk][tr];   // LDS.128
            float2 b2 = *(const float2*)&Ws[buf][kk][tc];   // LDS.64
            acc[0][0] = fmaf(a4.x, b2.x, acc[0][0]); acc[0][1] = fmaf(a4.x, b2.y, acc[0][1]);
            acc[1][0] = fmaf(a4.y, b2.x, acc[1][0]); acc[1][1] = fmaf(a4.y, b2.y, acc[1][1]);
            acc[2][0] = fmaf(a4.z, b2.x, acc[2][0]); acc[2][1] = fmaf(a4.z, b2.y, acc[2][1]);
            acc[3][0] = fmaf(a4.w, b2.x, acc[3][0]); acc[3][1] = fmaf(a4.w, b2.y, acc[3][1]);
        }
        if (c0 + 1 < NC) {
            #pragma unroll
            for (int l = 0; l < 2; l++) {
                int r = ar + l * 32;
                As[buf^1][ac+0][r] = pa[l].x; As[buf^1][ac+1][r] = pa[l].y;
                As[buf^1][ac+2][r] = pa[l].z; As[buf^1][ac+3][r] = pa[l].w;
            }
            Ws[buf^1][ac+0][ar] = pw.x; Ws[buf^1][ac+1][ar] = pw.y;
            Ws[buf^1][ac+2][ar] = pw.z; Ws[buf^1][ac+3][ar] = pw.w;
            __syncthreads();
            buf ^= 1;
        }
    }

    #pragma unroll
    for (int r = 0; r < 4; r++) {
        int row = row0 + tr + r;
        float rs = rowscale ? rowscale[row] : 0.0f;
        #pragma unroll
        for (int c = 0; c < 2; c++) {
            int col = col0 + tc + c;
            float v = acc[r][c];
            if (bias)  v += bias[col];
            if (biasd) v = fmaf(biasd[col], rs, v);
            C[(size_t)row * ldc + col] = v;
        }
    }
}

// ---------------- edge kernel: branchless CSR stream ----------------
// S[i,:] = sum_e relu(HB_i + HJ_{j_e} + EpC_e), e over row i's compacted edges
__global__ void edge_kernel(const float* __restrict__ C,
                            const unsigned* __restrict__ EpC,
                            const unsigned short* __restrict__ Jidx,
                            const int* __restrict__ off, const int* __restrict__ idg,
                            float* __restrict__ S)
{
    const int i    = blockIdx.x;
    const int tid  = threadIdx.x;
    const int w    = tid >> 5;
    const int lane = tid & 31;

    __shared__ float s_sh[8][MD];

    const float2 hb2 = *(const float2*)(C + (size_t)i * CW + 2 * lane);
    const int cnt  = idg[i];
    const int base = off[i];
    const unsigned*       ep = EpC + (size_t)base * 32;
    const unsigned short* jx = Jidx + base;

    float acc0 = 0.f, acc1 = 0.f;

    // warp w handles 4-edge chunks at cb = 4*(w + 8*t)
    for (int cb = w * 4; cb < cnt; cb += 32) {
        int nrem = cnt - cb;
        ushort4 j4 = *(const ushort4*)(jx + cb);      // uniform, 8B-aligned (base%4==0)
        unsigned pe[4]; float2 hj[4];
        #pragma unroll
        for (int u = 0; u < 4; u++) {
            if (u < nrem) {
                pe[u] = ep[(size_t)(cb + u) * 32 + lane];                  // coalesced
                int j = (u == 0) ? j4.x : (u == 1) ? j4.y : (u == 2) ? j4.z : j4.w;
                hj[u] = *(const float2*)(C + (size_t)j * CW + MD + 2 * lane);
            }
        }
        #pragma unroll
        for (int u = 0; u < 4; u++) {
            if (u < nrem) {
                float2 ef = __half22float2(*(const __half2*)&pe[u]);
                acc0 += fmaxf(hb2.x + hj[u].x + ef.x, 0.f);
                acc1 += fmaxf(hb2.y + hj[u].y + ef.y, 0.f);
            }
        }
    }

    s_sh[w][lane]      = acc0;   // m = lane
    s_sh[w][lane + 32] = acc1;   // m = lane + 32
    __syncthreads();

    if (tid < MD) {
        float s = 0.f;
        #pragma unroll
        for (int ww = 0; ww < 8; ww++) s += s_sh[ww][tid];
        S[i * MD + tid] = s;
    }
}

// ---------------- elementwise GRU update ----------------
__global__ void gru_kernel(const float* __restrict__ GI, const float* __restrict__ C,
                           const float* __restrict__ Hprev, float* __restrict__ Hout)
{
    int idx = blockIdx.x * blockDim.x + threadIdx.x;
    int i = idx >> 7;
    int d = idx & (ND - 1);
    const float* gi = GI + (size_t)i * 3 * ND;
    const float* gh = C + (size_t)i * CW + 2 * MD;     // GH section
    float r = 1.f / (1.f + __expf(-(gi[d]          + gh[d])));
    float z = 1.f / (1.f + __expf(-(gi[ND + d]     + gh[ND + d])));
    float narg = gi[2 * ND + d] + r * gh[2 * ND + d];
    float n = 1.f - 2.f / (__expf(2.f * narg) + 1.f);   // tanh
    float h = Hprev[idx];
    Hout[idx] = (1.f - z) * n + z * h;
}

// ---------------- launch ----------------
extern "C" void kernel_launch(void* const* d_in, const int* in_sizes, int n_in,
                              void* d_out, int out_size)
{
    const float* X    = (const float*)d_in[0];
    const int*   A    = (const int*)  d_in[1];
    const float* E    = (const float*)d_in[2];
    const float* W1   = (const float*)d_in[3];
    const float* b1   = (const float*)d_in[4];
    const float* W2   = (const float*)d_in[5];
    const float* b2   = (const float*)d_in[6];
    const float* W_ih = (const float*)d_in[7];
    const float* b_ih = (const float*)d_in[8];
    const float* W_hh = (const float*)d_in[9];
    const float* b_hh = (const float*)d_in[10];

    float *C, *S, *DEG, *GI, *H1, *H2, *Wcat, *bcat, *Wc, *bc;
    int *IDG, *OFF;
    unsigned* EPC;
    unsigned short* JIDX;
    cudaGetSymbolAddress((void**)&C,    g_C);
    cudaGetSymbolAddress((void**)&S,    g_S);
    cudaGetSymbolAddress((void**)&DEG,  g_deg);
    cudaGetSymbolAddress((void**)&IDG,  g_idg);
    cudaGetSymbolAddress((void**)&OFF,  g_off);
    cudaGetSymbolAddress((void**)&GI,   g_GI);
    cudaGetSymbolAddress((void**)&H1,   g_H1);
    cudaGetSymbolAddress((void**)&H2,   g_H2);
    cudaGetSymbolAddress((void**)&Wcat, g_Wcat);
    cudaGetSymbolAddress((void**)&bcat, g_bcat);
    cudaGetSymbolAddress((void**)&Wc,   g_Wc);
    cudaGetSymbolAddress((void**)&bc,   g_bc);
    cudaGetSymbolAddress((void**)&EPC,  g_EpC);
    cudaGetSymbolAddress((void**)&JIDX, g_Jidx);

    // one-time (per call) precomputes
    pack_kernel<<<(CW * ND) / 256, 256>>>(W1, b1, W_hh, b_hh, Wcat, bcat);
    wc_kernel<<<97, 256>>>(W_ih, W2, b2, Wc, bc);
    deg_kernel<<<(NN * 32) / 256, 256>>>(A, IDG, DEG);
    scan_kernel<<<1, NN>>>(IDG, OFF);
    ep_kernel<<<NN, 256>>>(E, A, W1, OFF, EPC, JIDX);

    const float* Hprev = X;
    for (int t = 0; t < 3; t++) {
        float* Hout = (t == 2) ? (float*)d_out : (t == 0 ? H1 : H2);

        // C = Hprev @ Wcat^T + bcat   -> [HBint | HJint | GH]
        gemm_kernel<128><<<dim3(CW / 32, 16), 256>>>(Hprev, ND, Wcat, ND, bcat,
                                                     nullptr, nullptr, C, CW);

        // masked relu-sum over compacted edges
        edge_kernel<<<NN, 256>>>(C, EPC, JIDX, OFF, IDG, S);

        // GI = S @ Wc^T + b_ih + deg*bc
        gemm_kernel<64><<<dim3((3 * ND) / 32, 16), 256>>>(S, MD, Wc, MD, b_ih,
                                                          bc, DEG, GI, 3 * ND);

        // GRU update
        gru_kernel<<<(NN * ND) / 256, 256>>>(GI, C, Hprev, Hout);

        Hprev = Hout;
    }
}

// round 10
// speedup vs baseline: 2.0419x; 1.0298x over previous
#include <cuda_runtime.h>
#include <cuda_fp16.h>
#include <math.h>

#define NN   1024
#define ND   128
#define ED   16
#define MD   64
#define IND  272   // 2*ND + ED
#define CW   512   // fused pre-GEMM width: 64 (HBint) + 64 (HJint) + 384 (GH)

// ---------------- scratch (no allocations allowed) ----------------
__device__ float g_C   [NN * CW];
__device__ float g_S   [NN * MD];
__device__ float g_deg [NN];           // degree (float)
__device__ int   g_idg [NN];           // degree (int)
__device__ int   g_off [NN];           // CSR row offsets (padded to 4)
__device__ float g_GI  [NN * 3 * ND];
__device__ float g_H1  [NN * ND];
__device__ float g_H2  [NN * ND];
__device__ float g_Wcat[CW * ND];
__device__ float g_bcat[CW];
__device__ float g_Wc  [3 * ND * MD];  // W_ih @ W2
__device__ float g_bc  [3 * ND];       // W_ih @ b2
__device__ unsigned g_HJh[NN * 32];    // HJ as fp16x2 (m, m+32) — 128 KB, L1-resident
// Compacted Ep: edge e -> 32 u32 (fp16x2 per lane: m, m+32)
__device__ unsigned       g_EpC [(size_t)NN * NN * 32 + (size_t)8 * NN * 32];
__device__ unsigned short g_Jidx[(size_t)NN * NN + 8 * NN + 16];

// ---------------- pack kernel: build Wcat/bcat (HB/HJ rows interleaved) ----------------
__global__ void pack_kernel(const float* __restrict__ W1, const float* __restrict__ b1,
                            const float* __restrict__ W_hh, const float* __restrict__ b_hh,
                            float* __restrict__ Wcat, float* __restrict__ bcat)
{
    int idx = blockIdx.x * blockDim.x + threadIdx.x;
    int r = idx >> 7;
    int c = idx & 127;
    float v;
    if (r < MD) {                       // HB section: interleaved Wi rows
        int m = (r >> 1) + ((r & 1) << 5);
        v = W1[(size_t)m * IND + c];
    } else if (r < 2 * MD) {            // HJ section: interleaved Wj rows
        int rr = r - MD;
        int m = (rr >> 1) + ((rr & 1) << 5);
        v = W1[(size_t)m * IND + ND + c];
    } else {
        v = W_hh[(size_t)(r - 2 * MD) * ND + c];
    }
    Wcat[idx] = v;
    if (idx < CW) {
        float b;
        if (idx < MD) {
            int m = (idx >> 1) + ((idx & 1) << 5);
            b = b1[m];
        }
        else if (idx < 2 * MD) b = 0.f;
        else                   b = b_hh[idx - 2 * MD];
        bcat[idx] = b;
    }
}

// ---------------- precompute Wc = W_ih @ W2, bc = W_ih @ b2 ----------------
__global__ void wc_kernel(const float* __restrict__ W_ih, const float* __restrict__ W2,
                          const float* __restrict__ b2,
                          float* __restrict__ Wc, float* __restrict__ bc)
{
    int bid = blockIdx.x;
    if (bid < 96) {
        int idx = bid * 256 + threadIdx.x;
        int r = idx >> 6;
        int s = idx & 63;
        float acc = 0.f;
        #pragma unroll 8
        for (int m = 0; m < MD; m++)
            acc = fmaf(W_ih[(size_t)r * MD + m], W2[(size_t)m * MD + s], acc);
        Wc[idx] = acc;
    } else {
        for (int r = threadIdx.x; r < 3 * ND; r += blockDim.x) {
            float acc = 0.f;
            #pragma unroll 8
            for (int m = 0; m < MD; m++)
                acc = fmaf(W_ih[(size_t)r * MD + m], b2[m], acc);
            bc[r] = acc;
        }
    }
}

// ---------------- degree kernel: one warp per row ----------------
__global__ void deg_kernel(const int* __restrict__ A, int* __restrict__ idg,
                           float* __restrict__ deg)
{
    int gtid = blockIdx.x * blockDim.x + threadIdx.x;
    int row  = gtid >> 5;
    int lane = gtid & 31;
    if (row >= NN) return;
    const int4* Arow = (const int4*)(A + (size_t)row * NN);
    int s = 0;
    #pragma unroll
    for (int q = 0; q < 8; q++) {
        int4 v = Arow[lane + q * 32];
        s += v.x + v.y + v.z + v.w;
    }
    #pragma unroll
    for (int o = 16; o; o >>= 1) s += __shfl_xor_sync(0xffffffffu, s, o);
    if (lane == 0) { idg[row] = s; deg[row] = (float)s; }
}

// ---------------- scan kernel: shfl-based exclusive prefix of padded degrees ----------------
__global__ void scan_kernel(const int* __restrict__ idg, int* __restrict__ off)
{
    __shared__ int wsum[32];
    int tid  = threadIdx.x;
    int lane = tid & 31;
    int wid  = tid >> 5;
    int pad = (idg[tid] + 3) & ~3;
    int v = pad;
    #pragma unroll
    for (int o = 1; o < 32; o <<= 1) {
        int n = __shfl_up_sync(0xffffffffu, v, o);
        if (lane >= o) v += n;
    }
    if (lane == 31) wsum[wid] = v;
    __syncthreads();
    if (wid == 0) {
        int s = wsum[lane];
        #pragma unroll
        for (int o = 1; o < 32; o <<= 1) {
            int n = __shfl_up_sync(0xffffffffu, s, o);
            if (lane >= o) s += n;
        }
        wsum[lane] = s;
    }
    __syncthreads();
    int add = wid ? wsum[wid - 1] : 0;
    off[tid] = add + v - pad;          // exclusive, padded
}

// ---------------- Ep precompute: compacted CSR write ----------------
__global__ void ep_kernel(const float* __restrict__ E, const int* __restrict__ A,
                          const float* __restrict__ W1, const int* __restrict__ off,
                          unsigned* __restrict__ EpC, unsigned short* __restrict__ Jidx)
{
    const int i    = blockIdx.x;
    const int tid  = threadIdx.x;
    const int w    = tid >> 5;
    const int lane = tid & 31;

    __shared__ float s_e[8][8][16];   // [warp][edge][q]
    __shared__ int   wcnt[8];

    float we0[ED], we1[ED];
    {
        const float4* p0 = (const float4*)(W1 + (size_t)lane        * IND + 2 * ND);
        const float4* p1 = (const float4*)(W1 + (size_t)(lane + 32) * IND + 2 * ND);
        #pragma unroll
        for (int q = 0; q < 4; q++) {
            float4 v = p0[q];
            we0[4*q+0] = v.x; we0[4*q+1] = v.y; we0[4*q+2] = v.z; we0[4*q+3] = v.w;
            float4 u = p1[q];
            we1[4*q+0] = u.x; we1[4*q+1] = u.y; we1[4*q+2] = u.z; we1[4*q+3] = u.w;
        }
    }

    const int jbase = w * 128;
    const int* Arow = A + (size_t)i * NN + jbase;

    unsigned bal[4];
    int myact = 0;
    #pragma unroll
    for (int s = 0; s < 4; s++) {
        int a = Arow[s * 32 + lane];
        bal[s] = __ballot_sync(0xffffffffu, a != 0);
        myact += __popc(bal[s]);
    }
    if (lane == 0) wcnt[w] = myact;
    __syncthreads();
    int pos = off[i];
    for (int ww = 0; ww < w; ww++) pos += wcnt[ww];

    const float4* E4 = (const float4*)(E + ((size_t)i * NN + jbase) * ED);

    for (int c = 0; c < 16; c++) {          // 16 chunks x 8 edges
        ((float4*)s_e[w])[lane] = E4[c * 32 + lane];   // coalesced stage
        __syncwarp();
        #pragma unroll
        for (int u = 0; u < 8; u++) {
            int jloc = c * 8 + u;
            if (!((bal[jloc >> 5] >> (jloc & 31)) & 1u)) continue;
            const float* ep = s_e[w][u];
            float v0 = 0.f, v1 = 0.f;
            #pragma unroll
            for (int q = 0; q < ED; q++) {
                float e = ep[q];
                v0 = fmaf(e, we0[q], v0);
                v1 = fmaf(e, we1[q], v1);
            }
            unsigned p;
            asm("cvt.rn.f16x2.f32 %0, %1, %2;" : "=r"(p) : "f"(v1), "f"(v0));
            EpC[(size_t)pos * 32 + lane] = p;
            if (lane == 0) Jidx[pos] = (unsigned short)(jbase + jloc);
            pos++;
        }
        __syncwarp();
    }
}

// ---------------- GEMM: C = A @ W^T + bias + rowscale*biasd ----------------
// 64x32 tile, 256 threads, 4x2 micro; smem transposed [k][row] -> LDS.128/LDS.64.
template<int K>
__global__ void gemm_kernel(const float* __restrict__ A, int lda,
                            const float* __restrict__ W, int ldw,
                            const float* __restrict__ bias,
                            const float* __restrict__ biasd,
                            const float* __restrict__ rowscale,
                            float* __restrict__ C, int ldc)
{
    __shared__ float As[2][32][68];
    __shared__ float Ws[2][32][36];
    constexpr int NC = K / 32;
    const int tid  = threadIdx.x;
    const int row0 = blockIdx.y * 64;
    const int col0 = blockIdx.x * 32;
    const int tr = (tid >> 4) * 4;
    const int tc = (tid & 15) * 2;
    const int ar = tid >> 3;
    const int ac = (tid & 7) * 4;

    float acc[4][2] = {};

    #pragma unroll
    for (int l = 0; l < 2; l++) {
        int r = ar + l * 32;
        float4 av = *(const float4*)&A[(size_t)(row0 + r) * lda + ac];
        As[0][ac+0][r] = av.x; As[0][ac+1][r] = av.y;
        As[0][ac+2][r] = av.z; As[0][ac+3][r] = av.w;
    }
    {
        float4 wv = *(const float4*)&W[(size_t)(col0 + ar) * ldw + ac];
        Ws[0][ac+0][ar] = wv.x; Ws[0][ac+1][ar] = wv.y;
        Ws[0][ac+2][ar] = wv.z; Ws[0][ac+3][ar] = wv.w;
    }
    __syncthreads();

    int buf = 0;
    #pragma unroll
    for (int c0 = 0; c0 < NC; c0++) {
        float4 pa[2], pw;
        if (c0 + 1 < NC) {
            #pragma unroll
            for (int l = 0; l < 2; l++) {
                int r = ar + l * 32;
                pa[l] = *(const float4*)&A[(size_t)(row0 + r) * lda + (c0 + 1) * 32 + ac];
            }
            pw = *(const float4*)&W[(size_t)(col0 + ar) * ldw + (c0 + 1) * 32 + ac];
        }
        #pragma unroll
        for (int kk = 0; kk < 32; kk++) {
            float4 a4 = *(const float4*)&As[buf][kk][tr];
            float2 b2 = *(const float2*)&Ws[buf][kk][tc];
            acc[0][0] = fmaf(a4.x, b2.x, acc[0][0]); acc[0][1] = fmaf(a4.x, b2.y, acc[0][1]);
            acc[1][0] = fmaf(a4.y, b2.x, acc[1][0]); acc[1][1] = fmaf(a4.y, b2.y, acc[1][1]);
            acc[2][0] = fmaf(a4.z, b2.x, acc[2][0]); acc[2][1] = fmaf(a4.z, b2.y, acc[2][1]);
            acc[3][0] = fmaf(a4.w, b2.x, acc[3][0]); acc[3][1] = fmaf(a4.w, b2.y, acc[3][1]);
        }
        if (c0 + 1 < NC) {
            #pragma unroll
            for (int l = 0; l < 2; l++) {
                int r = ar + l * 32;
                As[buf^1][ac+0][r] = pa[l].x; As[buf^1][ac+1][r] = pa[l].y;
                As[buf^1][ac+2][r] = pa[l].z; As[buf^1][ac+3][r] = pa[l].w;
            }
            Ws[buf^1][ac+0][ar] = pw.x; Ws[buf^1][ac+1][ar] = pw.y;
            Ws[buf^1][ac+2][ar] = pw.z; Ws[buf^1][ac+3][ar] = pw.w;
            __syncthreads();
            buf ^= 1;
        }
    }

    #pragma unroll
    for (int r = 0; r < 4; r++) {
        int row = row0 + tr + r;
        float rs = rowscale ? rowscale[row] : 0.0f;
        #pragma unroll
        for (int c = 0; c < 2; c++) {
            int col = col0 + tc + c;
            float v = acc[r][c];
            if (bias)  v += bias[col];
            if (biasd) v = fmaf(biasd[col], rs, v);
            C[(size_t)row * ldc + col] = v;
        }
    }
}

// ---------------- HJ convert: C's HJ section -> compact fp16x2 table (128 KB) ----------------
__global__ void hjconv_kernel(const float* __restrict__ C, unsigned* __restrict__ HJh)
{
    int idx = blockIdx.x * blockDim.x + threadIdx.x;   // NN*32
    int j = idx >> 5;
    int m = idx & 31;
    float2 v = *(const float2*)(C + (size_t)j * CW + MD + 2 * m);
    unsigned p;
    asm("cvt.rn.f16x2.f32 %0, %1, %2;" : "=r"(p) : "f"(v.y), "f"(v.x));
    HJh[idx] = p;
}

// ---------------- edge kernel: CSR stream + L1-resident fp16 HJ table ----------------
// S[i,:] = sum_e relu(HB_i + HJ_{j_e} + EpC_e)
__global__ void edge_kernel(const float* __restrict__ C,
                            const unsigned* __restrict__ HJh,
                            const unsigned* __restrict__ EpC,
                            const unsigned short* __restrict__ Jidx,
                            const int* __restrict__ off, const int* __restrict__ idg,
                            float* __restrict__ S)
{
    const int i    = blockIdx.x;
    const int tid  = threadIdx.x;
    const int w    = tid >> 5;
    const int lane = tid & 31;

    __shared__ float s_sh[8][MD];

    const float2 hb2 = *(const float2*)(C + (size_t)i * CW + 2 * lane);
    const int cnt  = idg[i];
    const int base = off[i];
    const unsigned*       ep = EpC + (size_t)base * 32;
    const unsigned short* jx = Jidx + base;

    float acc0 = 0.f, acc1 = 0.f;

    // warp w handles 8-edge chunks at cb = 8*w + 64*t
    for (int cb = w * 8; cb < cnt; cb += 64) {
        int nrem = cnt - cb;
        int jv[8];
        {
            ushort4 ja = *(const ushort4*)(jx + cb);          // base%4==0, cb%8==0 -> 8B aligned
            jv[0]=ja.x; jv[1]=ja.y; jv[2]=ja.z; jv[3]=ja.w;
            if (nrem > 4) {
                ushort4 jb = *(const ushort4*)(jx + cb + 4);
                jv[4]=jb.x; jv[5]=jb.y; jv[6]=jb.z; jv[7]=jb.w;
            } else { jv[4]=jv[5]=jv[6]=jv[7]=0; }
        }
        unsigned pe[8], ph[8];
        #pragma unroll
        for (int u = 0; u < 8; u++) {
            if (u < nrem) {
                pe[u] = ep[(size_t)(cb + u) * 32 + lane];     // coalesced 128B (DRAM/L2 stream)
                ph[u] = HJh[jv[u] * 32 + lane];               // L1-resident table
            }
        }
        #pragma unroll
        for (int u = 0; u < 8; u++) {
            if (u < nrem) {
                __half2 s2 = __hadd2(*(const __half2*)&pe[u], *(const __half2*)&ph[u]);
                float2 sf = __half22float2(s2);
                acc0 += fmaxf(hb2.x + sf.x, 0.f);
                acc1 += fmaxf(hb2.y + sf.y, 0.f);
            }
        }
    }

    s_sh[w][lane]      = acc0;   // m = lane
    s_sh[w][lane + 32] = acc1;   // m = lane + 32
    __syncthreads();

    if (tid < MD) {
        float s = 0.f;
        #pragma unroll
        for (int ww = 0; ww < 8; ww++) s += s_sh[ww][tid];
        S[i * MD + tid] = s;
    }
}

// ---------------- elementwise GRU update ----------------
__global__ void gru_kernel(const float* __restrict__ GI, const float* __restrict__ C,
                           const float* __restrict__ Hprev, float* __restrict__ Hout)
{
    int idx = blockIdx.x * blockDim.x + threadIdx.x;
    int i = idx >> 7;
    int d = idx & (ND - 1);
    const float* gi = GI + (size_t)i * 3 * ND;
    const float* gh = C + (size_t)i * CW + 2 * MD;
    float r = 1.f / (1.f + __expf(-(gi[d]          + gh[d])));
    float z = 1.f / (1.f + __expf(-(gi[ND + d]     + gh[ND + d])));
    float narg = gi[2 * ND + d] + r * gh[2 * ND + d];
    float n = 1.f - 2.f / (__expf(2.f * narg) + 1.f);   // tanh
    float h = Hprev[idx];
    Hout[idx] = (1.f - z) * n + z * h;
}

// ---------------- launch ----------------
extern "C" void kernel_launch(void* const* d_in, const int* in_sizes, int n_in,
                              void* d_out, int out_size)
{
    const float* X    = (const float*)d_in[0];
    const int*   A    = (const int*)  d_in[1];
    const float* E    = (const float*)d_in[2];
    const float* W1   = (const float*)d_in[3];
    const float* b1   = (const float*)d_in[4];
    const float* W2   = (const float*)d_in[5];
    const float* b2   = (const float*)d_in[6];
    const float* W_ih = (const float*)d_in[7];
    const float* b_ih = (const float*)d_in[8];
    const float* W_hh = (const float*)d_in[9];
    const float* b_hh = (const float*)d_in[10];

    float *C, *S, *DEG, *GI, *H1, *H2, *Wcat, *bcat, *Wc, *bc;
    int *IDG, *OFF;
    unsigned *EPC, *HJH;
    unsigned short* JIDX;
    cudaGetSymbolAddress((void**)&C,    g_C);
    cudaGetSymbolAddress((void**)&S,    g_S);
    cudaGetSymbolAddress((void**)&DEG,  g_deg);
    cudaGetSymbolAddress((void**)&IDG,  g_idg);
    cudaGetSymbolAddress((void**)&OFF,  g_off);
    cudaGetSymbolAddress((void**)&GI,   g_GI);
    cudaGetSymbolAddress((void**)&H1,   g_H1);
    cudaGetSymbolAddress((void**)&H2,   g_H2);
    cudaGetSymbolAddress((void**)&Wcat, g_Wcat);
    cudaGetSymbolAddress((void**)&bcat, g_bcat);
    cudaGetSymbolAddress((void**)&Wc,   g_Wc);
    cudaGetSymbolAddress((void**)&bc,   g_bc);
    cudaGetSymbolAddress((void**)&EPC,  g_EpC);
    cudaGetSymbolAddress((void**)&HJH,  g_HJh);
    cudaGetSymbolAddress((void**)&JIDX, g_Jidx);

    // one-time (per call) precomputes
    pack_kernel<<<(CW * ND) / 256, 256>>>(W1, b1, W_hh, b_hh, Wcat, bcat);
    wc_kernel<<<97, 256>>>(W_ih, W2, b2, Wc, bc);
    deg_kernel<<<(NN * 32) / 256, 256>>>(A, IDG, DEG);
    scan_kernel<<<1, NN>>>(IDG, OFF);
    ep_kernel<<<NN, 256>>>(E, A, W1, OFF, EPC, JIDX);

    const float* Hprev = X;
    for (int t = 0; t < 3; t++) {
        float* Hout = (t == 2) ? (float*)d_out : (t == 0 ? H1 : H2);

        // C = Hprev @ Wcat^T + bcat   -> [HBint | HJint | GH]
        gemm_kernel<128><<<dim3(CW / 32, 16), 256>>>(Hprev, ND, Wcat, ND, bcat,
                                                     nullptr, nullptr, C, CW);

        // compact fp16 HJ table (L1-resident in edge kernel)
        hjconv_kernel<<<(NN * 32) / 256, 256>>>(C, HJH);

        // relu-sum over compacted edges
        edge_kernel<<<NN, 256>>>(C, HJH, EPC, JIDX, OFF, IDG, S);

        // GI = S @ Wc^T + b_ih + deg*bc
        gemm_kernel<64><<<dim3((3 * ND) / 32, 16), 256>>>(S, MD, Wc, MD, b_ih,
                                                          bc, DEG, GI, 3 * ND);

        // GRU update
        gru_kernel<<<(NN * ND) / 256, 256>>>(GI, C, Hprev, Hout);

        Hprev = Hout;
    }
}

// round 11
// speedup vs baseline: 2.0760x; 1.0167x over previous
#include <cuda_runtime.h>
#include <cuda_fp16.h>
#include <math.h>

#define NN   1024
#define ND   128
#define ED   16
#define MD   64
#define IND  272   // 2*ND + ED
#define CW   512   // fused pre-GEMM width: 64 (HBint) + 64 (HJint) + 384 (GH)

// ---------------- scratch (no allocations allowed) ----------------
__device__ float g_C   [NN * CW];
__device__ float g_S   [NN * MD];
__device__ float g_deg [NN];
__device__ int   g_idg [NN];
__device__ int   g_off [NN];
__device__ float g_GI  [NN * 3 * ND];
__device__ float g_H1  [NN * ND];
__device__ float g_H2  [NN * ND];
__device__ float g_Wcat[CW * ND];
__device__ float g_bcat[CW];
__device__ float g_Wc  [3 * ND * MD];
__device__ float g_bc  [3 * ND];
__device__ unsigned g_HJh[NN * 32];    // HJ fp16x2 (m, m+32) — 128 KB, L1-resident
__device__ unsigned       g_EpC [(size_t)NN * NN * 32 + (size_t)8 * NN * 32];
__device__ unsigned short g_Jidx[(size_t)NN * NN + 8 * NN + 16];

// ---------------- pack kernel ----------------
__global__ void pack_kernel(const float* __restrict__ W1, const float* __restrict__ b1,
                            const float* __restrict__ W_hh, const float* __restrict__ b_hh,
                            float* __restrict__ Wcat, float* __restrict__ bcat)
{
    int idx = blockIdx.x * blockDim.x + threadIdx.x;
    int r = idx >> 7;
    int c = idx & 127;
    float v;
    if (r < MD) {
        int m = (r >> 1) + ((r & 1) << 5);
        v = W1[(size_t)m * IND + c];
    } else if (r < 2 * MD) {
        int rr = r - MD;
        int m = (rr >> 1) + ((rr & 1) << 5);
        v = W1[(size_t)m * IND + ND + c];
    } else {
        v = W_hh[(size_t)(r - 2 * MD) * ND + c];
    }
    Wcat[idx] = v;
    if (idx < CW) {
        float b;
        if (idx < MD) {
            int m = (idx >> 1) + ((idx & 1) << 5);
            b = b1[m];
        }
        else if (idx < 2 * MD) b = 0.f;
        else                   b = b_hh[idx - 2 * MD];
        bcat[idx] = b;
    }
}

// ---------------- Wc = W_ih @ W2, bc = W_ih @ b2 ----------------
__global__ void wc_kernel(const float* __restrict__ W_ih, const float* __restrict__ W2,
                          const float* __restrict__ b2,
                          float* __restrict__ Wc, float* __restrict__ bc)
{
    int bid = blockIdx.x;
    if (bid < 96) {
        int idx = bid * 256 + threadIdx.x;
        int r = idx >> 6;
        int s = idx & 63;
        float acc = 0.f;
        #pragma unroll 8
        for (int m = 0; m < MD; m++)
            acc = fmaf(W_ih[(size_t)r * MD + m], W2[(size_t)m * MD + s], acc);
        Wc[idx] = acc;
    } else {
        for (int r = threadIdx.x; r < 3 * ND; r += blockDim.x) {
            float acc = 0.f;
            #pragma unroll 8
            for (int m = 0; m < MD; m++)
                acc = fmaf(W_ih[(size_t)r * MD + m], b2[m], acc);
            bc[r] = acc;
        }
    }
}

// ---------------- degree kernel ----------------
__global__ void deg_kernel(const int* __restrict__ A, int* __restrict__ idg,
                           float* __restrict__ deg)
{
    int gtid = blockIdx.x * blockDim.x + threadIdx.x;
    int row  = gtid >> 5;
    int lane = gtid & 31;
    if (row >= NN) return;
    const int4* Arow = (const int4*)(A + (size_t)row * NN);
    int s = 0;
    #pragma unroll
    for (int q = 0; q < 8; q++) {
        int4 v = Arow[lane + q * 32];
        s += v.x + v.y + v.z + v.w;
    }
    #pragma unroll
    for (int o = 16; o; o >>= 1) s += __shfl_xor_sync(0xffffffffu, s, o);
    if (lane == 0) { idg[row] = s; deg[row] = (float)s; }
}

// ---------------- scan kernel (shfl) ----------------
__global__ void scan_kernel(const int* __restrict__ idg, int* __restrict__ off)
{
    __shared__ int wsum[32];
    int tid  = threadIdx.x;
    int lane = tid & 31;
    int wid  = tid >> 5;
    int pad = (idg[tid] + 3) & ~3;
    int v = pad;
    #pragma unroll
    for (int o = 1; o < 32; o <<= 1) {
        int n = __shfl_up_sync(0xffffffffu, v, o);
        if (lane >= o) v += n;
    }
    if (lane == 31) wsum[wid] = v;
    __syncthreads();
    if (wid == 0) {
        int s = wsum[lane];
        #pragma unroll
        for (int o = 1; o < 32; o <<= 1) {
            int n = __shfl_up_sync(0xffffffffu, s, o);
            if (lane >= o) s += n;
        }
        wsum[lane] = s;
    }
    __syncthreads();
    int add = wid ? wsum[wid - 1] : 0;
    off[tid] = add + v - pad;
}

// ---------------- Ep precompute: compacted CSR (streaming writes) ----------------
__global__ void ep_kernel(const float* __restrict__ E, const int* __restrict__ A,
                          const float* __restrict__ W1, const int* __restrict__ off,
                          unsigned* __restrict__ EpC, unsigned short* __restrict__ Jidx)
{
    const int i    = blockIdx.x;
    const int tid  = threadIdx.x;
    const int w    = tid >> 5;
    const int lane = tid & 31;

    __shared__ float s_e[8][8][16];
    __shared__ int   wcnt[8];

    float we0[ED], we1[ED];
    {
        const float4* p0 = (const float4*)(W1 + (size_t)lane        * IND + 2 * ND);
        const float4* p1 = (const float4*)(W1 + (size_t)(lane + 32) * IND + 2 * ND);
        #pragma unroll
        for (int q = 0; q < 4; q++) {
            float4 v = p0[q];
            we0[4*q+0] = v.x; we0[4*q+1] = v.y; we0[4*q+2] = v.z; we0[4*q+3] = v.w;
            float4 u = p1[q];
            we1[4*q+0] = u.x; we1[4*q+1] = u.y; we1[4*q+2] = u.z; we1[4*q+3] = u.w;
        }
    }

    const int jbase = w * 128;
    const int* Arow = A + (size_t)i * NN + jbase;

    unsigned bal[4];
    int myact = 0;
    #pragma unroll
    for (int s = 0; s < 4; s++) {
        int a = Arow[s * 32 + lane];
        bal[s] = __ballot_sync(0xffffffffu, a != 0);
        myact += __popc(bal[s]);
    }
    if (lane == 0) wcnt[w] = myact;
    __syncthreads();
    int pos = off[i];
    for (int ww = 0; ww < w; ww++) pos += wcnt[ww];

    const float4* E4 = (const float4*)(E + ((size_t)i * NN + jbase) * ED);

    for (int c = 0; c < 16; c++) {
        ((float4*)s_e[w])[lane] = E4[c * 32 + lane];
        __syncwarp();
        #pragma unroll
        for (int u = 0; u < 8; u++) {
            int jloc = c * 8 + u;
            if (!((bal[jloc >> 5] >> (jloc & 31)) & 1u)) continue;
            const float* ep = s_e[w][u];
            float v0 = 0.f, v1 = 0.f;
            #pragma unroll
            for (int q = 0; q < ED; q++) {
                float e = ep[q];
                v0 = fmaf(e, we0[q], v0);
                v1 = fmaf(e, we1[q], v1);
            }
            unsigned p;
            asm("cvt.rn.f16x2.f32 %0, %1, %2;" : "=r"(p) : "f"(v1), "f"(v0));
            __stcg(&EpC[(size_t)pos * 32 + lane], p);      // streaming store
            if (lane == 0) Jidx[pos] = (unsigned short)(jbase + jloc);
            pos++;
        }
        __syncwarp();
    }
}

// ---------------- GEMM: C = A @ W^T + bias + rowscale*biasd (+ optional HJh emit) ----------------
template<int K>
__global__ void gemm_kernel(const float* __restrict__ A, int lda,
                            const float* __restrict__ W, int ldw,
                            const float* __restrict__ bias,
                            const float* __restrict__ biasd,
                            const float* __restrict__ rowscale,
                            float* __restrict__ C, int ldc,
                            unsigned* __restrict__ HJh)
{
    __shared__ float As[2][32][68];
    __shared__ float Ws[2][32][36];
    constexpr int NC = K / 32;
    const int tid  = threadIdx.x;
    const int row0 = blockIdx.y * 64;
    const int col0 = blockIdx.x * 32;
    const int tr = (tid >> 4) * 4;
    const int tc = (tid & 15) * 2;
    const int ar = tid >> 3;
    const int ac = (tid & 7) * 4;

    float acc[4][2] = {};

    #pragma unroll
    for (int l = 0; l < 2; l++) {
        int r = ar + l * 32;
        float4 av = *(const float4*)&A[(size_t)(row0 + r) * lda + ac];
        As[0][ac+0][r] = av.x; As[0][ac+1][r] = av.y;
        As[0][ac+2][r] = av.z; As[0][ac+3][r] = av.w;
    }
    {
        float4 wv = *(const float4*)&W[(size_t)(col0 + ar) * ldw + ac];
        Ws[0][ac+0][ar] = wv.x; Ws[0][ac+1][ar] = wv.y;
        Ws[0][ac+2][ar] = wv.z; Ws[0][ac+3][ar] = wv.w;
    }
    __syncthreads();

    int buf = 0;
    #pragma unroll
    for (int c0 = 0; c0 < NC; c0++) {
        float4 pa[2], pw;
        if (c0 + 1 < NC) {
            #pragma unroll
            for (int l = 0; l < 2; l++) {
                int r = ar + l * 32;
                pa[l] = *(const float4*)&A[(size_t)(row0 + r) * lda + (c0 + 1) * 32 + ac];
            }
            pw = *(const float4*)&W[(size_t)(col0 + ar) * ldw + (c0 + 1) * 32 + ac];
        }
        #pragma unroll
        for (int kk = 0; kk < 32; kk++) {
            float4 a4 = *(const float4*)&As[buf][kk][tr];
            float2 b2 = *(const float2*)&Ws[buf][kk][tc];
            acc[0][0] = fmaf(a4.x, b2.x, acc[0][0]); acc[0][1] = fmaf(a4.x, b2.y, acc[0][1]);
            acc[1][0] = fmaf(a4.y, b2.x, acc[1][0]); acc[1][1] = fmaf(a4.y, b2.y, acc[1][1]);
            acc[2][0] = fmaf(a4.z, b2.x, acc[2][0]); acc[2][1] = fmaf(a4.z, b2.y, acc[2][1]);
            acc[3][0] = fmaf(a4.w, b2.x, acc[3][0]); acc[3][1] = fmaf(a4.w, b2.y, acc[3][1]);
        }
        if (c0 + 1 < NC) {
            #pragma unroll
            for (int l = 0; l < 2; l++) {
                int r = ar + l * 32;
                As[buf^1][ac+0][r] = pa[l].x; As[buf^1][ac+1][r] = pa[l].y;
                As[buf^1][ac+2][r] = pa[l].z; As[buf^1][ac+3][r] = pa[l].w;
            }
            Ws[buf^1][ac+0][ar] = pw.x; Ws[buf^1][ac+1][ar] = pw.y;
            Ws[buf^1][ac+2][ar] = pw.z; Ws[buf^1][ac+3][ar] = pw.w;
            __syncthreads();
            buf ^= 1;
        }
    }

    const bool emit_hj = (HJh != nullptr) && (col0 >= MD) && (col0 < 2 * MD);
    #pragma unroll
    for (int r = 0; r < 4; r++) {
        int row = row0 + tr + r;
        float rs = rowscale ? rowscale[row] : 0.0f;
        float v0 = acc[r][0], v1 = acc[r][1];
        int c0i = col0 + tc, c1i = col0 + tc + 1;
        if (bias)  { v0 += bias[c0i];            v1 += bias[c1i]; }
        if (biasd) { v0 = fmaf(biasd[c0i], rs, v0); v1 = fmaf(biasd[c1i], rs, v1); }
        C[(size_t)row * ldc + c0i] = v0;
        C[(size_t)row * ldc + c1i] = v1;
        if (emit_hj) {
            int m = (col0 + tc - MD) >> 1;     // cols (64+2m, 64+2m+1) = units (m, m+32)
            unsigned p;
            asm("cvt.rn.f16x2.f32 %0, %1, %2;" : "=r"(p) : "f"(v1), "f"(v0));
            HJh[row * 32 + m] = p;
        }
    }
}

// ---------------- edge kernel: streaming Ep (__ldcg) + L1-resident HJh + fp32 adds ----------------
__global__ void edge_kernel(const float* __restrict__ C,
                            const unsigned* __restrict__ HJh,
                            const unsigned* __restrict__ EpC,
                            const unsigned short* __restrict__ Jidx,
                            const int* __restrict__ off, const int* __restrict__ idg,
                            float* __restrict__ S)
{
    const int i    = blockIdx.x;
    const int tid  = threadIdx.x;
    const int w    = tid >> 5;
    const int lane = tid & 31;

    __shared__ float s_sh[8][MD];

    const float2 hb2 = *(const float2*)(C + (size_t)i * CW + 2 * lane);
    const int cnt  = idg[i];
    const int base = off[i];
    const unsigned*       ep = EpC + (size_t)base * 32;
    const unsigned short* jx = Jidx + base;

    float acc0 = 0.f, acc1 = 0.f;

    for (int cb = w * 8; cb < cnt; cb += 64) {
        int nrem = cnt - cb;
        int jv[8];
        {
            ushort4 ja = *(const ushort4*)(jx + cb);
            jv[0]=ja.x; jv[1]=ja.y; jv[2]=ja.z; jv[3]=ja.w;
            if (nrem > 4) {
                ushort4 jb = *(const ushort4*)(jx + cb + 4);
                jv[4]=jb.x; jv[5]=jb.y; jv[6]=jb.z; jv[7]=jb.w;
            } else { jv[4]=jv[5]=jv[6]=jv[7]=0; }
        }
        unsigned pe[8], ph[8];
        #pragma unroll
        for (int u = 0; u < 8; u++) {
            if (u < nrem) {
                pe[u] = __ldcg(&ep[(size_t)(cb + u) * 32 + lane]);  // stream: bypass L1
                ph[u] = HJh[jv[u] * 32 + lane];                      // L1-resident table
            }
        }
        #pragma unroll
        for (int u = 0; u < 8; u++) {
            if (u < nrem) {
                float2 ef = __half22float2(*(const __half2*)&pe[u]);
                float2 hf = __half22float2(*(const __half2*)&ph[u]);
                acc0 += fmaxf(hb2.x + hf.x + ef.x, 0.f);   // fp32 adds
                acc1 += fmaxf(hb2.y + hf.y + ef.y, 0.f);
            }
        }
    }

    s_sh[w][lane]      = acc0;
    s_sh[w][lane + 32] = acc1;
    __syncthreads();

    if (tid < MD) {
        float s = 0.f;
        #pragma unroll
        for (int ww = 0; ww < 8; ww++) s += s_sh[ww][tid];
        S[i * MD + tid] = s;
    }
}

// ---------------- elementwise GRU update ----------------
__global__ void gru_kernel(const float* __restrict__ GI, const float* __restrict__ C,
                           const float* __restrict__ Hprev, float* __restrict__ Hout)
{
    int idx = blockIdx.x * blockDim.x + threadIdx.x;
    int i = idx >> 7;
    int d = idx & (ND - 1);
    const float* gi = GI + (size_t)i * 3 * ND;
    const float* gh = C + (size_t)i * CW + 2 * MD;
    float r = 1.f / (1.f + __expf(-(gi[d]          + gh[d])));
    float z = 1.f / (1.f + __expf(-(gi[ND + d]     + gh[ND + d])));
    float narg = gi[2 * ND + d] + r * gh[2 * ND + d];
    float n = 1.f - 2.f / (__expf(2.f * narg) + 1.f);   // tanh
    float h = Hprev[idx];
    Hout[idx] = (1.f - z) * n + z * h;
}

// ---------------- launch ----------------
extern "C" void kernel_launch(void* const* d_in, const int* in_sizes, int n_in,
                              void* d_out, int out_size)
{
    const float* X    = (const float*)d_in[0];
    const int*   A    = (const int*)  d_in[1];
    const float* E    = (const float*)d_in[2];
    const float* W1   = (const float*)d_in[3];
    const float* b1   = (const float*)d_in[4];
    const float* W2   = (const float*)d_in[5];
    const float* b2   = (const float*)d_in[6];
    const float* W_ih = (const float*)d_in[7];
    const float* b_ih = (const float*)d_in[8];
    const float* W_hh = (const float*)d_in[9];
    const float* b_hh = (const float*)d_in[10];

    float *C, *S, *DEG, *GI, *H1, *H2, *Wcat, *bcat, *Wc, *bc;
    int *IDG, *OFF;
    unsigned *EPC, *HJH;
    unsigned short* JIDX;
    cudaGetSymbolAddress((void**)&C,    g_C);
    cudaGetSymbolAddress((void**)&S,    g_S);
    cudaGetSymbolAddress((void**)&DEG,  g_deg);
    cudaGetSymbolAddress((void**)&IDG,  g_idg);
    cudaGetSymbolAddress((void**)&OFF,  g_off);
    cudaGetSymbolAddress((void**)&GI,   g_GI);
    cudaGetSymbolAddress((void**)&H1,   g_H1);
    cudaGetSymbolAddress((void**)&H2,   g_H2);
    cudaGetSymbolAddress((void**)&Wcat, g_Wcat);
    cudaGetSymbolAddress((void**)&bcat, g_bcat);
    cudaGetSymbolAddress((void**)&Wc,   g_Wc);
    cudaGetSymbolAddress((void**)&bc,   g_bc);
    cudaGetSymbolAddress((void**)&EPC,  g_EpC);
    cudaGetSymbolAddress((void**)&HJH,  g_HJh);
    cudaGetSymbolAddress((void**)&JIDX, g_Jidx);

    // one-time (per call) precomputes
    pack_kernel<<<(CW * ND) / 256, 256>>>(W1, b1, W_hh, b_hh, Wcat, bcat);
    wc_kernel<<<97, 256>>>(W_ih, W2, b2, Wc, bc);
    deg_kernel<<<(NN * 32) / 256, 256>>>(A, IDG, DEG);
    scan_kernel<<<1, NN>>>(IDG, OFF);
    ep_kernel<<<NN, 256>>>(E, A, W1, OFF, EPC, JIDX);

    const float* Hprev = X;
    for (int t = 0; t < 3; t++) {
        float* Hout = (t == 2) ? (float*)d_out : (t == 0 ? H1 : H2);

        // C = Hprev @ Wcat^T + bcat -> [HBint | HJint | GH]; HJh emitted in epilogue
        gemm_kernel<128><<<dim3(CW / 32, 16), 256>>>(Hprev, ND, Wcat, ND, bcat,
                                                     nullptr, nullptr, C, CW, HJH);

        // relu-sum over compacted edges
        edge_kernel<<<NN, 256>>>(C, HJH, EPC, JIDX, OFF, IDG, S);

        // GI = S @ Wc^T + b_ih + deg*bc
        gemm_kernel<64><<<dim3((3 * ND) / 32, 16), 256>>>(S, MD, Wc, MD, b_ih,
                                                          bc, DEG, GI, 3 * ND, nullptr);

        // GRU update
        gru_kernel<<<(NN * ND) / 256, 256>>>(GI, C, Hprev, Hout);

        Hprev = Hout;
    }
}

// round 12
// speedup vs baseline: 2.2068x; 1.0630x over previous
#include <cuda_runtime.h>
#include <cuda_fp16.h>
#include <math.h>

#define NN   1024
#define ND   128
#define ED   16
#define MD   64
#define IND  272   // 2*ND + ED
#define CW   512   // fused pre-GEMM width: 64 (HBint) + 64 (HJint) + 384 (GH)

// ---------------- scratch (no allocations allowed) ----------------
__device__ float g_C   [NN * CW];
__device__ float g_S   [NN * MD];
__device__ float g_deg [NN];
__device__ int   g_idg [NN];
__device__ float g_H1  [NN * ND];
__device__ float g_H2  [NN * ND];
__device__ float g_Wcat[CW * ND];
__device__ float g_bcat[CW];
__device__ float g_Wc  [3 * ND * MD];
__device__ float g_bc  [3 * ND];
__device__ unsigned g_HJh[NN * 32];    // HJ fp16x2 (m, m+32) — 128 KB, L1-resident
// Fixed-stride compacted Ep: row i's edges at [i*1024, i*1024+deg_i)
__device__ unsigned       g_EpC [(size_t)NN * 1024 * 32];
__device__ unsigned short g_Jidx[(size_t)NN * 1024 + 8];

// ---------------- pack kernel ----------------
__global__ void pack_kernel(const float* __restrict__ W1, const float* __restrict__ b1,
                            const float* __restrict__ W_hh, const float* __restrict__ b_hh,
                            float* __restrict__ Wcat, float* __restrict__ bcat)
{
    int idx = blockIdx.x * blockDim.x + threadIdx.x;
    int r = idx >> 7;
    int c = idx & 127;
    float v;
    if (r < MD) {
        int m = (r >> 1) + ((r & 1) << 5);
        v = W1[(size_t)m * IND + c];
    } else if (r < 2 * MD) {
        int rr = r - MD;
        int m = (rr >> 1) + ((rr & 1) << 5);
        v = W1[(size_t)m * IND + ND + c];
    } else {
        v = W_hh[(size_t)(r - 2 * MD) * ND + c];
    }
    Wcat[idx] = v;
    if (idx < CW) {
        float b;
        if (idx < MD) {
            int m = (idx >> 1) + ((idx & 1) << 5);
            b = b1[m];
        }
        else if (idx < 2 * MD) b = 0.f;
        else                   b = b_hh[idx - 2 * MD];
        bcat[idx] = b;
    }
}

// ---------------- Wc = W_ih @ W2, bc = W_ih @ b2 ----------------
__global__ void wc_kernel(const float* __restrict__ W_ih, const float* __restrict__ W2,
                          const float* __restrict__ b2,
                          float* __restrict__ Wc, float* __restrict__ bc)
{
    int bid = blockIdx.x;
    if (bid < 96) {
        int idx = bid * 256 + threadIdx.x;
        int r = idx >> 6;
        int s = idx & 63;
        float acc = 0.f;
        #pragma unroll 8
        for (int m = 0; m < MD; m++)
            acc = fmaf(W_ih[(size_t)r * MD + m], W2[(size_t)m * MD + s], acc);
        Wc[idx] = acc;
    } else {
        for (int r = threadIdx.x; r < 3 * ND; r += blockDim.x) {
            float acc = 0.f;
            #pragma unroll 8
            for (int m = 0; m < MD; m++)
                acc = fmaf(W_ih[(size_t)r * MD + m], b2[m], acc);
            bc[r] = acc;
        }
    }
}

// ---------------- Ep precompute: fixed-stride compacted CSR; also computes deg ----------------
__global__ void ep_kernel(const float* __restrict__ E, const int* __restrict__ A,
                          const float* __restrict__ W1,
                          unsigned* __restrict__ EpC, unsigned short* __restrict__ Jidx,
                          int* __restrict__ idg, float* __restrict__ deg)
{
    const int i    = blockIdx.x;
    const int tid  = threadIdx.x;
    const int w    = tid >> 5;
    const int lane = tid & 31;

    __shared__ float s_e[8][8][16];
    __shared__ int   wcnt[8];

    float we0[ED], we1[ED];
    {
        const float4* p0 = (const float4*)(W1 + (size_t)lane        * IND + 2 * ND);
        const float4* p1 = (const float4*)(W1 + (size_t)(lane + 32) * IND + 2 * ND);
        #pragma unroll
        for (int q = 0; q < 4; q++) {
            float4 v = p0[q];
            we0[4*q+0] = v.x; we0[4*q+1] = v.y; we0[4*q+2] = v.z; we0[4*q+3] = v.w;
            float4 u = p1[q];
            we1[4*q+0] = u.x; we1[4*q+1] = u.y; we1[4*q+2] = u.z; we1[4*q+3] = u.w;
        }
    }

    const int jbase = w * 128;
    const int* Arow = A + (size_t)i * NN + jbase;

    unsigned bal[4];
    int myact = 0;
    #pragma unroll
    for (int s = 0; s < 4; s++) {
        int a = Arow[s * 32 + lane];
        bal[s] = __ballot_sync(0xffffffffu, a != 0);
        myact += __popc(bal[s]);
    }
    if (lane == 0) wcnt[w] = myact;
    __syncthreads();
    int pos = i << 10;                         // fixed row stride 1024
    for (int ww = 0; ww < w; ww++) pos += wcnt[ww];
    if (tid == 0) {
        int t = 0;
        #pragma unroll
        for (int k = 0; k < 8; k++) t += wcnt[k];
        idg[i] = t; deg[i] = (float)t;
    }

    const float4* E4 = (const float4*)(E + ((size_t)i * NN + jbase) * ED);

    for (int c = 0; c < 16; c++) {
        ((float4*)s_e[w])[lane] = E4[c * 32 + lane];
        __syncwarp();
        #pragma unroll
        for (int u = 0; u < 8; u++) {
            int jloc = c * 8 + u;
            if (!((bal[jloc >> 5] >> (jloc & 31)) & 1u)) continue;
            const float4* e4 = (const float4*)s_e[w][u];   // 64B-aligned
            float4 ea = e4[0], eb = e4[1], ec = e4[2], ed = e4[3];
            float v0, v1;
            v0  = ea.x * we0[0];  v1  = ea.x * we1[0];
            v0 = fmaf(ea.y, we0[1],  v0); v1 = fmaf(ea.y, we1[1],  v1);
            v0 = fmaf(ea.z, we0[2],  v0); v1 = fmaf(ea.z, we1[2],  v1);
            v0 = fmaf(ea.w, we0[3],  v0); v1 = fmaf(ea.w, we1[3],  v1);
            v0 = fmaf(eb.x, we0[4],  v0); v1 = fmaf(eb.x, we1[4],  v1);
            v0 = fmaf(eb.y, we0[5],  v0); v1 = fmaf(eb.y, we1[5],  v1);
            v0 = fmaf(eb.z, we0[6],  v0); v1 = fmaf(eb.z, we1[6],  v1);
            v0 = fmaf(eb.w, we0[7],  v0); v1 = fmaf(eb.w, we1[7],  v1);
            v0 = fmaf(ec.x, we0[8],  v0); v1 = fmaf(ec.x, we1[8],  v1);
            v0 = fmaf(ec.y, we0[9],  v0); v1 = fmaf(ec.y, we1[9],  v1);
            v0 = fmaf(ec.z, we0[10], v0); v1 = fmaf(ec.z, we1[10], v1);
            v0 = fmaf(ec.w, we0[11], v0); v1 = fmaf(ec.w, we1[11], v1);
            v0 = fmaf(ed.x, we0[12], v0); v1 = fmaf(ed.x, we1[12], v1);
            v0 = fmaf(ed.y, we0[13], v0); v1 = fmaf(ed.y, we1[13], v1);
            v0 = fmaf(ed.z, we0[14], v0); v1 = fmaf(ed.z, we1[14], v1);
            v0 = fmaf(ed.w, we0[15], v0); v1 = fmaf(ed.w, we1[15], v1);
            unsigned p;
            asm("cvt.rn.f16x2.f32 %0, %1, %2;" : "=r"(p) : "f"(v1), "f"(v0));
            __stcg(&EpC[(size_t)pos * 32 + lane], p);
            if (lane == 0) Jidx[pos] = (unsigned short)(jbase + jloc);
            pos++;
        }
        __syncwarp();
    }
}

// ---------------- GEMM: C = A @ W^T + bias (+ HJh emit) ----------------
template<int K>
__global__ void gemm_kernel(const float* __restrict__ A, int lda,
                            const float* __restrict__ W, int ldw,
                            const float* __restrict__ bias,
                            float* __restrict__ C, int ldc,
                            unsigned* __restrict__ HJh)
{
    __shared__ float As[2][32][68];
    __shared__ float Ws[2][32][36];
    constexpr int NC = K / 32;
    const int tid  = threadIdx.x;
    const int row0 = blockIdx.y * 64;
    const int col0 = blockIdx.x * 32;
    const int tr = (tid >> 4) * 4;
    const int tc = (tid & 15) * 2;
    const int ar = tid >> 3;
    const int ac = (tid & 7) * 4;

    float acc[4][2] = {};

    #pragma unroll
    for (int l = 0; l < 2; l++) {
        int r = ar + l * 32;
        float4 av = *(const float4*)&A[(size_t)(row0 + r) * lda + ac];
        As[0][ac+0][r] = av.x; As[0][ac+1][r] = av.y;
        As[0][ac+2][r] = av.z; As[0][ac+3][r] = av.w;
    }
    {
        float4 wv = *(const float4*)&W[(size_t)(col0 + ar) * ldw + ac];
        Ws[0][ac+0][ar] = wv.x; Ws[0][ac+1][ar] = wv.y;
        Ws[0][ac+2][ar] = wv.z; Ws[0][ac+3][ar] = wv.w;
    }
    __syncthreads();

    int buf = 0;
    #pragma unroll
    for (int c0 = 0; c0 < NC; c0++) {
        float4 pa[2], pw;
        if (c0 + 1 < NC) {
            #pragma unroll
            for (int l = 0; l < 2; l++) {
                int r = ar + l * 32;
                pa[l] = *(const float4*)&A[(size_t)(row0 + r) * lda + (c0 + 1) * 32 + ac];
            }
            pw = *(const float4*)&W[(size_t)(col0 + ar) * ldw + (c0 + 1) * 32 + ac];
        }
        #pragma unroll
        for (int kk = 0; kk < 32; kk++) {
            float4 a4 = *(const float4*)&As[buf][kk][tr];
            float2 b2 = *(const float2*)&Ws[buf][kk][tc];
            acc[0][0] = fmaf(a4.x, b2.x, acc[0][0]); acc[0][1] = fmaf(a4.x, b2.y, acc[0][1]);
            acc[1][0] = fmaf(a4.y, b2.x, acc[1][0]); acc[1][1] = fmaf(a4.y, b2.y, acc[1][1]);
            acc[2][0] = fmaf(a4.z, b2.x, acc[2][0]); acc[2][1] = fmaf(a4.z, b2.y, acc[2][1]);
            acc[3][0] = fmaf(a4.w, b2.x, acc[3][0]); acc[3][1] = fmaf(a4.w, b2.y, acc[3][1]);
        }
        if (c0 + 1 < NC) {
            #pragma unroll
            for (int l = 0; l < 2; l++) {
                int r = ar + l * 32;
                As[buf^1][ac+0][r] = pa[l].x; As[buf^1][ac+1][r] = pa[l].y;
                As[buf^1][ac+2][r] = pa[l].z; As[buf^1][ac+3][r] = pa[l].w;
            }
            Ws[buf^1][ac+0][ar] = pw.x; Ws[buf^1][ac+1][ar] = pw.y;
            Ws[buf^1][ac+2][ar] = pw.z; Ws[buf^1][ac+3][ar] = pw.w;
            __syncthreads();
            buf ^= 1;
        }
    }

    const bool emit_hj = (HJh != nullptr) && (col0 >= MD) && (col0 < 2 * MD);
    #pragma unroll
    for (int r = 0; r < 4; r++) {
        int row = row0 + tr + r;
        float v0 = acc[r][0], v1 = acc[r][1];
        int c0i = col0 + tc, c1i = col0 + tc + 1;
        if (bias) { v0 += bias[c0i]; v1 += bias[c1i]; }
        C[(size_t)row * ldc + c0i] = v0;
        C[(size_t)row * ldc + c1i] = v1;
        if (emit_hj) {
            int m = (col0 + tc - MD) >> 1;
            unsigned p;
            asm("cvt.rn.f16x2.f32 %0, %1, %2;" : "=r"(p) : "f"(v1), "f"(v0));
            HJh[row * 32 + m] = p;
        }
    }
}

// ---------------- edge kernel: streaming Ep (__ldcg) + L1-resident HJh ----------------
__global__ void edge_kernel(const float* __restrict__ C,
                            const unsigned* __restrict__ HJh,
                            const unsigned* __restrict__ EpC,
                            const unsigned short* __restrict__ Jidx,
                            const int* __restrict__ idg,
                            float* __restrict__ S)
{
    const int i    = blockIdx.x;
    const int tid  = threadIdx.x;
    const int w    = tid >> 5;
    const int lane = tid & 31;

    __shared__ float s_sh[8][MD];

    const float2 hb2 = *(const float2*)(C + (size_t)i * CW + 2 * lane);
    const int cnt  = idg[i];
    const int base = i << 10;
    const unsigned*       ep = EpC + (size_t)base * 32;
    const unsigned short* jx = Jidx + base;

    float acc0 = 0.f, acc1 = 0.f;

    for (int cb = w * 8; cb < cnt; cb += 64) {
        int nrem = cnt - cb;
        int jv[8];
        {
            ushort4 ja = *(const ushort4*)(jx + cb);
            jv[0]=ja.x; jv[1]=ja.y; jv[2]=ja.z; jv[3]=ja.w;
            if (nrem > 4) {
                ushort4 jb = *(const ushort4*)(jx + cb + 4);
                jv[4]=jb.x; jv[5]=jb.y; jv[6]=jb.z; jv[7]=jb.w;
            } else { jv[4]=jv[5]=jv[6]=jv[7]=0; }
        }
        unsigned pe[8], ph[8];
        #pragma unroll
        for (int u = 0; u < 8; u++) {
            if (u < nrem) {
                pe[u] = __ldcg(&ep[(size_t)(cb + u) * 32 + lane]);
                ph[u] = HJh[jv[u] * 32 + lane];
            }
        }
        #pragma unroll
        for (int u = 0; u < 8; u++) {
            if (u < nrem) {
                float2 ef = __half22float2(*(const __half2*)&pe[u]);
                float2 hf = __half22float2(*(const __half2*)&ph[u]);
                acc0 += fmaxf(hb2.x + hf.x + ef.x, 0.f);
                acc1 += fmaxf(hb2.y + hf.y + ef.y, 0.f);
            }
        }
    }

    s_sh[w][lane]      = acc0;
    s_sh[w][lane + 32] = acc1;
    __syncthreads();

    if (tid < MD) {
        float s = 0.f;
        #pragma unroll
        for (int ww = 0; ww < 8; ww++) s += s_sh[ww][tid];
        S[i * MD + tid] = s;
    }
}

// ---------------- fused GI + GRU kernel ----------------
// Block: 32 nodes (by) x 32 d-values (bx), 3 gates. GI = S@Wc^T + b_ih + deg*bc;
// then GRU with GH (in C) and Hprev -> Hout. Grid (4, 32), 256 threads.
__global__ void gi_gru_kernel(const float* __restrict__ S,
                              const float* __restrict__ Wc,
                              const float* __restrict__ b_ih,
                              const float* __restrict__ bc,
                              const float* __restrict__ deg,
                              const float* __restrict__ C,
                              const float* __restrict__ Hprev,
                              float* __restrict__ Hout)
{
    __shared__ float As[32][36];        // [kk][node]
    __shared__ float Wg[32][3][33];     // [kk][gate][d]

    const int tid = threadIdx.x;
    const int d0  = blockIdx.x * 32;
    const int i0  = blockIdx.y * 32;
    const int rg  = tid >> 5;           // 0..7 -> nodes i0+rg*4 .. +3
    const int dl  = tid & 31;
    const int d   = d0 + dl;

    float accr[4] = {}, accz[4] = {}, accn[4] = {};

    #pragma unroll
    for (int c0 = 0; c0 < 2; c0++) {
        // load S tile: 32 nodes x 32 k
        {
            int srow = tid >> 3;
            int kq   = (tid & 7) * 4;
            float4 v = *(const float4*)&S[(size_t)(i0 + srow) * MD + c0 * 32 + kq];
            As[kq+0][srow] = v.x; As[kq+1][srow] = v.y;
            As[kq+2][srow] = v.z; As[kq+3][srow] = v.w;
        }
        // load Wc tile: 96 gate-rows x 32 k
        #pragma unroll
        for (int l = 0; l < 3; l++) {
            int s    = tid + l * 256;
            int r96  = s >> 3;          // 0..95
            int kq   = (s & 7) * 4;
            int gate = r96 >> 5;
            int dd   = r96 & 31;
            int grow = gate * ND + d0 + dd;
            float4 v = *(const float4*)&Wc[(size_t)grow * MD + c0 * 32 + kq];
            Wg[kq+0][gate][dd] = v.x; Wg[kq+1][gate][dd] = v.y;
            Wg[kq+2][gate][dd] = v.z; Wg[kq+3][gate][dd] = v.w;
        }
        __syncthreads();
        #pragma unroll
        for (int kk = 0; kk < 32; kk++) {
            float4 a4 = *(const float4*)&As[kk][rg * 4];
            float br = Wg[kk][0][dl], bz = Wg[kk][1][dl], bn = Wg[kk][2][dl];
            accr[0] = fmaf(a4.x, br, accr[0]); accz[0] = fmaf(a4.x, bz, accz[0]); accn[0] = fmaf(a4.x, bn, accn[0]);
            accr[1] = fmaf(a4.y, br, accr[1]); accz[1] = fmaf(a4.y, bz, accz[1]); accn[1] = fmaf(a4.y, bn, accn[1]);
            accr[2] = fmaf(a4.z, br, accr[2]); accz[2] = fmaf(a4.z, bz, accz[2]); accn[2] = fmaf(a4.z, bn, accn[2]);
            accr[3] = fmaf(a4.w, br, accr[3]); accz[3] = fmaf(a4.w, bz, accz[3]); accn[3] = fmaf(a4.w, bn, accn[3]);
        }
        __syncthreads();
    }

    const float bir = b_ih[d], biz = b_ih[ND + d], bin = b_ih[2 * ND + d];
    const float bcr = bc[d],  bcz = bc[ND + d],  bcn = bc[2 * ND + d];

    #pragma unroll
    for (int q = 0; q < 4; q++) {
        int row = i0 + rg * 4 + q;
        float dg = deg[row];
        float gir = accr[q] + bir + dg * bcr;
        float giz = accz[q] + biz + dg * bcz;
        float gin = accn[q] + bin + dg * bcn;
        const float* gh = C + (size_t)row * CW + 2 * MD;
        float ghr = gh[d], ghz = gh[ND + d], ghn = gh[2 * ND + d];
        float r = 1.f / (1.f + __expf(-(gir + ghr)));
        float z = 1.f / (1.f + __expf(-(giz + ghz)));
        float narg = gin + r * ghn;
        float n = 1.f - 2.f / (__expf(2.f * narg) + 1.f);
        float h = Hprev[(size_t)row * ND + d];
        Hout[(size_t)row * ND + d] = (1.f - z) * n + z * h;
    }
}

// ---------------- launch ----------------
extern "C" void kernel_launch(void* const* d_in, const int* in_sizes, int n_in,
                              void* d_out, int out_size)
{
    const float* X    = (const float*)d_in[0];
    const int*   A    = (const int*)  d_in[1];
    const float* E    = (const float*)d_in[2];
    const float* W1   = (const float*)d_in[3];
    const float* b1   = (const float*)d_in[4];
    const float* W2   = (const float*)d_in[5];
    const float* b2   = (const float*)d_in[6];
    const float* W_ih = (const float*)d_in[7];
    const float* b_ih = (const float*)d_in[8];
    const float* W_hh = (const float*)d_in[9];
    const float* b_hh = (const float*)d_in[10];

    float *C, *S, *DEG, *H1, *H2, *Wcat, *bcat, *Wc, *bc;
    int *IDG;
    unsigned *EPC, *HJH;
    unsigned short* JIDX;
    cudaGetSymbolAddress((void**)&C,    g_C);
    cudaGetSymbolAddress((void**)&S,    g_S);
    cudaGetSymbolAddress((void**)&DEG,  g_deg);
    cudaGetSymbolAddress((void**)&IDG,  g_idg);
    cudaGetSymbolAddress((void**)&H1,   g_H1);
    cudaGetSymbolAddress((void**)&H2,   g_H2);
    cudaGetSymbolAddress((void**)&Wcat, g_Wcat);
    cudaGetSymbolAddress((void**)&bcat, g_bcat);
    cudaGetSymbolAddress((void**)&Wc,   g_Wc);
    cudaGetSymbolAddress((void**)&bc,   g_bc);
    cudaGetSymbolAddress((void**)&EPC,  g_EpC);
    cudaGetSymbolAddress((void**)&HJH,  g_HJh);
    cudaGetSymbolAddress((void**)&JIDX, g_Jidx);

    // one-time (per call) precomputes
    pack_kernel<<<(CW * ND) / 256, 256>>>(W1, b1, W_hh, b_hh, Wcat, bcat);
    wc_kernel<<<97, 256>>>(W_ih, W2, b2, Wc, bc);
    ep_kernel<<<NN, 256>>>(E, A, W1, EPC, JIDX, IDG, DEG);

    const float* Hprev = X;
    for (int t = 0; t < 3; t++) {
        float* Hout = (t == 2) ? (float*)d_out : (t == 0 ? H1 : H2);

        // C = Hprev @ Wcat^T + bcat -> [HBint | HJint | GH]; HJh emitted in epilogue
        gemm_kernel<128><<<dim3(CW / 32, 16), 256>>>(Hprev, ND, Wcat, ND, bcat,
                                                     C, CW, HJH);

        // relu-sum over compacted edges
        edge_kernel<<<NN, 256>>>(C, HJH, EPC, JIDX, IDG, S);

        // fused GI + GRU -> Hout
        gi_gru_kernel<<<dim3(4, 32), 256>>>(S, Wc, b_ih, bc, DEG, C, Hprev, Hout);

        Hprev = Hout;
    }
}